// round 12
// baseline (speedup 1.0000x reference)
#include <cuda_runtime.h>
#include <cuda_bf16.h>
#include <math.h>
#include <stdint.h>

#define C_    512
#define N_    16384
#define B_    4
#define NMAT  8
#define EPS_  1e-5f
#define NS_ITERS 6
#define KSPLIT 8
#define KSEG  (N_ / KSPLIT)       // 2048
#define PGRID 288                 // persistent grid (<= 2/SM co-residency)

#define MODE_COV     0
#define MODE_APPLY   4

// 128-tile engine SMEM: 4 tensors x 128 rows x 40(pad) bf16 = 10240B; stage 40960B; 2 stages
#define TEN_BYTES   10240
#define STAGE_BYTES 40960
#define SMEM_DYN    81920
// 64-tile engine SMEM (static): 4 tensors x 64 x 40 bf16 = 5120B; stage 20480B; 2 stages
#define TEN64   5120
#define STAGE64 20480

// ---------------- device scratch (no allocations allowed) ----------------
__device__ float g_mean[2][B_][C_];                  // [0]=content, [1]=style
__device__ float g_cov[NMAT][C_ * C_];
__device__ float g_covp[KSPLIT][NMAT][C_ * C_];      // split-K raw partials
__device__ float g_s[NMAT], g_sinv[NMAT];
__device__ __nv_bfloat16 g_xh[2][B_][C_][N_];        // centered hi  [src][b][c][n]
__device__ __nv_bfloat16 g_xm[2][B_][C_][N_];        // centered mid
__device__ __nv_bfloat16 g_th[B_][N_][C_];           // content^T centered hi
__device__ __nv_bfloat16 g_tm[B_][N_][C_];           // content^T centered mid
__device__ __nv_bfloat16 g_Yh[2][NMAT][C_ * C_], g_Ym[2][NMAT][C_ * C_];
__device__ __nv_bfloat16 g_Zh[2][NMAT][C_ * C_], g_Zm[2][NMAT][C_ * C_];
__device__ __nv_bfloat16 g_Gh[NMAT][C_ * C_], g_Gm[NMAT][C_ * C_];
__device__ __nv_bfloat16 g_Mh[B_][C_ * C_], g_Mm[B_][C_ * C_];

// grid-wide barrier state (epoch-snapshot makes graph replays safe)
__device__ unsigned g_arrive = 0;
__device__ unsigned g_release = 0;

// ---------------- PTX helpers (all sm_80+ features only) ----------------
__device__ __forceinline__ uint32_t smem_u32(const void* p) {
    uint32_t a;
    asm("{ .reg .u64 t; cvta.to.shared.u64 t, %1; cvt.u32.u64 %0, t; }" : "=r"(a) : "l"(p));
    return a;
}
#define CP_ASYNC(dst, src) asm volatile("cp.async.cg.shared.global [%0], [%1], 16;" :: "r"(dst), "l"(src))
#define CP_COMMIT()        asm volatile("cp.async.commit_group;" ::: "memory")
#define CP_WAIT1()         asm volatile("cp.async.wait_group 1;" ::: "memory")
#define CP_WAIT0()         asm volatile("cp.async.wait_group 0;" ::: "memory")

__device__ __forceinline__ void ldsm4(uint32_t* r, uint32_t addr) {
    asm volatile("ldmatrix.sync.aligned.m8n8.x4.shared.b16 {%0,%1,%2,%3}, [%4];"
        : "=r"(r[0]), "=r"(r[1]), "=r"(r[2]), "=r"(r[3]) : "r"(addr));
}
__device__ __forceinline__ void mma16816(float* c, const uint32_t* a, const uint32_t* b) {
    asm volatile("mma.sync.aligned.m16n8k16.row.col.f32.bf16.bf16.f32 "
        "{%0,%1,%2,%3}, {%4,%5,%6,%7}, {%8,%9}, {%0,%1,%2,%3};"
        : "+f"(c[0]), "+f"(c[1]), "+f"(c[2]), "+f"(c[3])
        : "r"(a[0]), "r"(a[1]), "r"(a[2]), "r"(a[3]), "r"(b[0]), "r"(b[1]));
}
__device__ __forceinline__ void split2(float v, __nv_bfloat16& h, __nv_bfloat16& m) {
    h = __float2bfloat16(v);
    m = __float2bfloat16(v - __bfloat162float(h));
}

// ---------------- fused means + center + split (single read of inputs) ----------------
__global__ __launch_bounds__(256) void means_split_kernel(
    const float* __restrict__ content, const float* __restrict__ style)
{
    int idx = blockIdx.x;
    int src = idx >> 11, b = (idx >> 9) & 3, c = idx & 511;
    const float4* X4 = (const float4*)((src ? style : content) + (size_t)(b * C_ + c) * N_);

    float4 v[16];
    float sum = 0.f;
#pragma unroll
    for (int j = 0; j < 16; j++) {
        v[j] = X4[threadIdx.x + j * 256];
        sum += (v[j].x + v[j].y) + (v[j].z + v[j].w);
    }
    __shared__ float red[256];
    red[threadIdx.x] = sum;
    __syncthreads();
    for (int s = 128; s; s >>= 1) {
        if (threadIdx.x < s) red[threadIdx.x] += red[threadIdx.x + s];
        __syncthreads();
    }
    float mu = red[0] * (1.0f / N_);
    if (threadIdx.x == 0) g_mean[src][b][c] = mu;

    __nv_bfloat162* H = (__nv_bfloat162*)&g_xh[src][b][c][0];
    __nv_bfloat162* M = (__nv_bfloat162*)&g_xm[src][b][c][0];
#pragma unroll
    for (int j = 0; j < 16; j++) {
        int i = threadIdx.x + j * 256;
        __nv_bfloat16 h0, m0, h1, m1, h2, m2, h3, m3;
        split2(v[j].x - mu, h0, m0); split2(v[j].y - mu, h1, m1);
        split2(v[j].z - mu, h2, m2); split2(v[j].w - mu, h3, m3);
        __nv_bfloat162 a, b2;
        a.x = h0; a.y = h1; b2.x = h2; b2.y = h3;
        H[2 * i] = a; H[2 * i + 1] = b2;
        a.x = m0; a.y = m1; b2.x = m2; b2.y = m3;
        M[2 * i] = a; M[2 * i + 1] = b2;
    }
}

__global__ __launch_bounds__(256) void transpose_kernel(const float* __restrict__ content)
{
    __shared__ float t[32][33];
    int b = blockIdx.z;
    int n0 = blockIdx.x * 32, c0 = blockIdx.y * 32;
    int tx = threadIdx.x & 31, ty = threadIdx.x >> 5;   // 32 x 8
    const float* X = content + (size_t)b * C_ * N_;
#pragma unroll
    for (int j = 0; j < 32; j += 8) {
        int c = c0 + ty + j;
        t[ty + j][tx] = X[(size_t)c * N_ + n0 + tx] - g_mean[0][b][c];
    }
    __syncthreads();
#pragma unroll
    for (int j = 0; j < 32; j += 8) {
        int n = n0 + ty + j, c = c0 + tx;
        __nv_bfloat16 h, m;
        split2(t[tx][ty + j], h, m);
        g_th[b][n][c] = h;
        g_tm[b][n][c] = m;
    }
}

// ---------------- cp.async stage fills ----------------
__device__ __forceinline__ void fill_stage(uint32_t sbase,
    const __nv_bfloat16* ah, const __nv_bfloat16* am,
    const __nv_bfloat16* bh, const __nv_bfloat16* bm,
    long sA, long sB, int tid)
{
#pragma unroll
    for (int t = tid; t < 512; t += 256) {
        int row = t >> 2, q = (t & 3) * 8;
        uint32_t d = sbase + (uint32_t)(row * 40 + q) * 2;
        long oa = (long)row * sA + q, ob = (long)row * sB + q;
        CP_ASYNC(d,                 ah + oa);
        CP_ASYNC(d + TEN_BYTES,     am + oa);
        CP_ASYNC(d + 2 * TEN_BYTES, bh + ob);
        CP_ASYNC(d + 3 * TEN_BYTES, bm + ob);
    }
}

__device__ __forceinline__ void fill_stage64(uint32_t sbase,
    const __nv_bfloat16* ah, const __nv_bfloat16* am,
    const __nv_bfloat16* bh, const __nv_bfloat16* bm, int tid)
{
    int row = tid >> 2, q = (tid & 3) * 8;              // 64 rows x 4 quads = 256 threads
    uint32_t d = sbase + (uint32_t)(row * 40 + q) * 2;
    long o = (long)row * C_ + q;
    CP_ASYNC(d,             ah + o);
    CP_ASYNC(d + TEN64,     am + o);
    CP_ASYNC(d + 2 * TEN64, bh + o);
    CP_ASYNC(d + 3 * TEN64, bm + o);
}

// ---------------- 64x64 tile job (C=512 GEMM, bf16 hi/mid 3-pass) ----------------
__device__ __forceinline__ void tile64(
    const __nv_bfloat16* __restrict__ Ah, const __nv_bfloat16* __restrict__ Am,
    const __nv_bfloat16* __restrict__ Bh, const __nv_bfloat16* __restrict__ Bm,
    __nv_bfloat16* __restrict__ dh, __nv_bfloat16* __restrict__ dm,
    int i0, int j0, bool isG, float alpha, bool mirror, uint32_t sb)
{
    int tid = threadIdx.x, wid = tid >> 5, l = tid & 31;
    int wr = wid & 3, wc = wid >> 2;                    // 4 (m) x 2 (n) warps

    uint32_t aoff = (uint32_t)(((wr * 16 + (l & 15)) * 40 + ((l >> 4) << 3)) * 2);
    uint32_t boff[2];
#pragma unroll
    for (int jp = 0; jp < 2; jp++) {
        int g = l >> 3;
        int row = wc * 32 + jp * 16 + (l & 7) + ((g >= 2) ? 8 : 0);
        boff[jp] = (uint32_t)((row * 40 + ((g & 1) << 3)) * 2);
    }

    float acc[4][4];
#pragma unroll
    for (int a = 0; a < 4; a++)
#pragma unroll
        for (int q = 0; q < 4; q++) acc[a][q] = 0.f;

    const int nch = C_ / 32;   // 16
    fill_stage64(sb, Ah, Am, Bh, Bm, tid); CP_COMMIT();
    fill_stage64(sb + STAGE64, Ah + 32, Am + 32, Bh + 32, Bm + 32, tid); CP_COMMIT();

    for (int c = 0; c < nch; c++) {
        if (c + 1 < nch) CP_WAIT1(); else CP_WAIT0();
        __syncthreads();
        uint32_t stb = sb + (uint32_t)(c & 1) * STAGE64;
#pragma unroll
        for (int kk = 0; kk < 2; kk++) {
            uint32_t kof = (uint32_t)kk * 32;
            uint32_t fa[4], fm[4], b0h[4], b0m[4], b1h[4], b1m[4];
            ldsm4(fa, stb + aoff + kof);
            ldsm4(fm, stb + TEN64 + aoff + kof);
            ldsm4(b0h, stb + 2 * TEN64 + boff[0] + kof);
            ldsm4(b0m, stb + 3 * TEN64 + boff[0] + kof);
            ldsm4(b1h, stb + 2 * TEN64 + boff[1] + kof);
            ldsm4(b1m, stb + 3 * TEN64 + boff[1] + kof);
            // 3 passes, 4 independent accumulators between RAW reuses
            mma16816(acc[0], fa, &b0h[0]);
            mma16816(acc[1], fa, &b0h[2]);
            mma16816(acc[2], fa, &b1h[0]);
            mma16816(acc[3], fa, &b1h[2]);
            mma16816(acc[0], fa, &b0m[0]);
            mma16816(acc[1], fa, &b0m[2]);
            mma16816(acc[2], fa, &b1m[0]);
            mma16816(acc[3], fa, &b1m[2]);
            mma16816(acc[0], fm, &b0h[0]);
            mma16816(acc[1], fm, &b0h[2]);
            mma16816(acc[2], fm, &b1h[0]);
            mma16816(acc[3], fm, &b1h[2]);
        }
        __syncthreads();
        if (c + 2 < nch) {
            long ko = (long)(c + 2) * 32;
            fill_stage64(sb + (uint32_t)(c & 1) * STAGE64,
                         Ah + ko, Am + ko, Bh + ko, Bm + ko, tid);
            CP_COMMIT();
        }
    }

    // epilogue
    int r0 = l >> 2, cp2 = (l & 3) * 2;
    int gia = i0 + wr * 16 + r0;                        // rows gia, gia+8
#pragma unroll
    for (int a = 0; a < 4; a++) {
        int gj = j0 + wc * 32 + a * 8 + cp2;            // cols gj, gj+1
        float v00 = acc[a][0], v01 = acc[a][1];
        float v10 = acc[a][2], v11 = acc[a][3];
        if (isG) {
            v00 = -0.5f * v00 + ((gj     == gia)     ? 1.5f : 0.f);
            v01 = -0.5f * v01 + ((gj + 1 == gia)     ? 1.5f : 0.f);
            v10 = -0.5f * v10 + ((gj     == gia + 8) ? 1.5f : 0.f);
            v11 = -0.5f * v11 + ((gj + 1 == gia + 8) ? 1.5f : 0.f);
        } else {
            v00 *= alpha; v01 *= alpha; v10 *= alpha; v11 *= alpha;
        }
        __nv_bfloat16 h00, m00, h01, m01, h10, m10, h11, m11;
        split2(v00, h00, m00); split2(v01, h01, m01);
        split2(v10, h10, m10); split2(v11, h11, m11);
        __nv_bfloat162 p;
        p.x = h00; p.y = h01; *(__nv_bfloat162*)&dh[(long)gia * C_ + gj] = p;
        p.x = m00; p.y = m01; *(__nv_bfloat162*)&dm[(long)gia * C_ + gj] = p;
        p.x = h10; p.y = h11; *(__nv_bfloat162*)&dh[(long)(gia + 8) * C_ + gj] = p;
        p.x = m10; p.y = m11; *(__nv_bfloat162*)&dm[(long)(gia + 8) * C_ + gj] = p;
        if (mirror) {
            dh[(long)gj * C_ + gia] = h00;           dm[(long)gj * C_ + gia] = m00;
            dh[(long)(gj + 1) * C_ + gia] = h01;     dm[(long)(gj + 1) * C_ + gia] = m01;
            dh[(long)gj * C_ + gia + 8] = h10;       dm[(long)gj * C_ + gia + 8] = m10;
            dh[(long)(gj + 1) * C_ + gia + 8] = h11; dm[(long)(gj + 1) * C_ + gia + 8] = m11;
        }
    }
}

// ---------------- persistent NS kernel: cov_reduce -> scale -> init -> 6x(G,YZ) -> M ----------------
__global__ __launch_bounds__(256, 2) void ns_persistent_kernel()
{
    __shared__ __align__(16) char sm64[2 * STAGE64];
    __shared__ float red[256];
    uint32_t sb = smem_u32(sm64);
    int tid = threadIdx.x, cta = blockIdx.x;

    unsigned base = 0, eps = 0;
    if (tid == 0) base = *(volatile unsigned*)&g_release;   // snapshot (graph-replay safe)

    // grid-wide barrier (sense via monotonically increasing release counter)
    auto gbar = [&]() {
        __syncthreads();
        if (tid == 0) {
            __threadfence();
            unsigned old = atomicAdd(&g_arrive, 1u);
            if (old == PGRID - 1) {
                atomicExch(&g_arrive, 0u);
                __threadfence();
                atomicExch(&g_release, base + eps + 1);
            } else {
                while (*(volatile unsigned*)&g_release - base < eps + 1) __nanosleep(128);
            }
            __threadfence();
        }
        eps++;
        __syncthreads();
    };

    // phase 0: fold split-K cov partials
    for (int i = cta * 256 + tid; i < NMAT * C_ * C_; i += PGRID * 256) {
        int m = i >> 18, r = i & (C_ * C_ - 1);
        float v = 0.f;
#pragma unroll
        for (int s = 0; s < KSPLIT; s++) v += g_covp[s][m][r];
        v *= 1.0f / (float)(N_ - 1);
        if ((r >> 9) == (r & 511)) v += EPS_;
        g_cov[m][r] = v;
    }
    gbar();

    // phase 1: spectral scale (8 CTAs work, deterministic in-CTA tree)
    if (cta < NMAT) {
        const float* covm = g_cov[cta];
        float ss = 0.f;
        for (int i = tid; i < C_ * C_; i += 256) {
            float v = covm[i];
            ss += v * v;
        }
        red[tid] = ss;
        __syncthreads();
        for (int s = 128; s; s >>= 1) {
            if (tid < s) red[tid] += red[tid + s];
            __syncthreads();
        }
        if (tid == 0) {
            float sc = sqrtf(red[0]) * (1.0f / 2.5f);
            g_s[cta] = sc;
            g_sinv[cta] = 1.0f / sc;
        }
    }
    gbar();

    // phase 2: Y0 = cov/s (split), Z0 = I
    for (int i = cta * 256 + tid; i < NMAT * C_ * C_; i += PGRID * 256) {
        int m = i >> 18, r = i & (C_ * C_ - 1);
        float v = g_cov[m][r] * g_sinv[m];
        __nv_bfloat16 h, mm;
        split2(v, h, mm);
        g_Yh[0][m][r] = h;
        g_Ym[0][m][r] = mm;
        bool dg = ((r >> 9) == (r & 511));
        g_Zh[0][m][r] = __float2bfloat16(dg ? 1.0f : 0.0f);
        g_Zm[0][m][r] = __float2bfloat16(0.0f);
    }
    gbar();

    // phases 3..: Newton-Schulz iterations
    for (int it = 0; it < NS_ITERS; it++) {
        int flag = it & 1;
        // --- G = (3I - Z*Y)/2 : 288 jobs = 8 mats x 36 sym tiles ---
        {
            int m = cta / 36, t = cta % 36;
            int by = 0;
            while (t >= 8 - by) { t -= 8 - by; by++; }
            int bx = by + t;
            int i0 = by * 64, j0 = bx * 64;
            tile64(g_Zh[flag][m] + (long)i0 * C_, g_Zm[flag][m] + (long)i0 * C_,
                   g_Yh[flag][m] + (long)j0 * C_, g_Ym[flag][m] + (long)j0 * C_,
                   g_Gh[m], g_Gm[m], i0, j0, true, 1.f, bx != by, sb);
        }
        gbar();
        // --- Ynew = Y*G, Znew = G*Z : 576 jobs, 2 per CTA ---
#pragma unroll
        for (int r2 = 0; r2 < 2; r2++) {
            int job = cta + PGRID * r2;
            int z = job / 36, t = job % 36;
            int by = 0;
            while (t >= 8 - by) { t -= 8 - by; by++; }
            int bx = by + t;
            int i0 = by * 64, j0 = bx * 64;
            int m = z & 7;
            if (z < 8)
                tile64(g_Yh[flag][m] + (long)i0 * C_, g_Ym[flag][m] + (long)i0 * C_,
                       g_Gh[m] + (long)j0 * C_,       g_Gm[m] + (long)j0 * C_,
                       g_Yh[flag ^ 1][m], g_Ym[flag ^ 1][m], i0, j0, false, 1.f, bx != by, sb);
            else
                tile64(g_Gh[m] + (long)i0 * C_,       g_Gm[m] + (long)i0 * C_,
                       g_Zh[flag][m] + (long)j0 * C_, g_Zm[flag][m] + (long)j0 * C_,
                       g_Zh[flag ^ 1][m], g_Zm[flag ^ 1][m], i0, j0, false, 1.f, bx != by, sb);
        }
        gbar();
    }

    // final phase: M = alpha * Y_style * Z_content^T (256 jobs, full 8x8 grid, no mirror)
    // NS_ITERS=6 -> final iterates live in buffer [0]
    if (cta < 256) {
        int b = cta >> 6, t = cta & 63;
        int by = t >> 3, bx = t & 7;
        int i0 = by * 64, j0 = bx * 64;
        float alpha = sqrtf(g_s[4 + b] / g_s[b]);
        tile64(g_Yh[0][4 + b] + (long)i0 * C_, g_Ym[0][4 + b] + (long)i0 * C_,
               g_Zh[0][b] + (long)j0 * C_,     g_Zm[0][b] + (long)j0 * C_,
               g_Mh[b], g_Mm[b], i0, j0, false, alpha, false, sb);
    }
}

// ---------------- 128-tile warp-MMA kernel (COV split-K + APPLY) ----------------
__global__ __launch_bounds__(256, 2) void mma_kernel(int mode, int flag, float* __restrict__ outp)
{
    int bx = blockIdx.x, by = blockIdx.y, bz = blockIdx.z;
    bool sym = (mode == MODE_COV);
    if (sym && by > bx) return;
    int i0 = by * 128, j0 = bx * 128;

    const __nv_bfloat16 *Ah, *Am, *Bh, *Bm;
    long sA, sB;
    int K;
    int mz = bz, sK = 0;
    if (mode == MODE_COV) {
        mz = bz & 7; sK = bz >> 3;
        int src = mz >> 2, b = mz & 3;
        long ks = (long)sK * KSEG;
        Ah = &g_xh[src][b][i0][0] + ks; Am = &g_xm[src][b][i0][0] + ks;
        Bh = &g_xh[src][b][j0][0] + ks; Bm = &g_xm[src][b][j0][0] + ks;
        sA = sB = N_; K = KSEG;
    } else {                                   // APPLY: out = M * Xc^T (+ s_mean)
        Ah = g_Mh[bz] + (long)i0 * C_;       Am = g_Mm[bz] + (long)i0 * C_;
        Bh = &g_th[bz][j0][0];               Bm = &g_tm[bz][j0][0];
        sA = sB = C_; K = C_;
    }

    extern __shared__ char dsm[];
    uint32_t sb = smem_u32(dsm);
    int tid = threadIdx.x, wid = tid >> 5, l = tid & 31;
    int wr = wid & 3, wc = wid >> 2;

    uint32_t aoff[2], boff[4];
#pragma unroll
    for (int t = 0; t < 2; t++)
        aoff[t] = (uint32_t)(((wr * 32 + t * 16 + (l & 15)) * 40 + ((l >> 4) << 3)) * 2);
#pragma unroll
    for (int jp = 0; jp < 4; jp++) {
        int g = l >> 3;
        int row = wc * 64 + jp * 16 + (l & 7) + ((g >= 2) ? 8 : 0);
        boff[jp] = (uint32_t)((row * 40 + ((g & 1) << 3)) * 2);
    }

    float acc[2][8][4];
#pragma unroll
    for (int t = 0; t < 2; t++)
#pragma unroll
        for (int j = 0; j < 8; j++)
#pragma unroll
            for (int q = 0; q < 4; q++) acc[t][j][q] = 0.f;

    int nch = K / 32;
    fill_stage(sb, Ah, Am, Bh, Bm, sA, sB, tid); CP_COMMIT();
    fill_stage(sb + STAGE_BYTES, Ah + 32, Am + 32, Bh + 32, Bm + 32, sA, sB, tid); CP_COMMIT();

    for (int c = 0; c < nch; c++) {
        if (c + 1 < nch) CP_WAIT1(); else CP_WAIT0();
        __syncthreads();
        uint32_t stb = sb + (uint32_t)(c & 1) * STAGE_BYTES;
#pragma unroll
        for (int kk = 0; kk < 2; kk++) {
            uint32_t kof = (uint32_t)kk * 32;
            uint32_t fa[2][4], fm[2][4];
            ldsm4(fa[0], stb + aoff[0] + kof);
            ldsm4(fa[1], stb + aoff[1] + kof);
            ldsm4(fm[0], stb + TEN_BYTES + aoff[0] + kof);
            ldsm4(fm[1], stb + TEN_BYTES + aoff[1] + kof);
#pragma unroll
            for (int jp = 0; jp < 4; jp++) {
                uint32_t bh[4], bm2[4];
                ldsm4(bh,  stb + 2 * TEN_BYTES + boff[jp] + kof);
                ldsm4(bm2, stb + 3 * TEN_BYTES + boff[jp] + kof);
                mma16816(acc[0][2 * jp],     fa[0], &bh[0]);
                mma16816(acc[0][2 * jp + 1], fa[0], &bh[2]);
                mma16816(acc[1][2 * jp],     fa[1], &bh[0]);
                mma16816(acc[1][2 * jp + 1], fa[1], &bh[2]);
                mma16816(acc[0][2 * jp],     fa[0], &bm2[0]);
                mma16816(acc[0][2 * jp + 1], fa[0], &bm2[2]);
                mma16816(acc[1][2 * jp],     fa[1], &bm2[0]);
                mma16816(acc[1][2 * jp + 1], fa[1], &bm2[2]);
                mma16816(acc[0][2 * jp],     fm[0], &bh[0]);
                mma16816(acc[0][2 * jp + 1], fm[0], &bh[2]);
                mma16816(acc[1][2 * jp],     fm[1], &bh[0]);
                mma16816(acc[1][2 * jp + 1], fm[1], &bh[2]);
            }
        }
        __syncthreads();
        if (c + 2 < nch) {
            long ko = (long)(c + 2) * 32;
            fill_stage(sb + (uint32_t)(c & 1) * STAGE_BYTES,
                       Ah + ko, Am + ko, Bh + ko, Bm + ko, sA, sB, tid);
            CP_COMMIT();
        }
    }

    int r0 = l >> 2, cp2 = (l & 3) * 2;
#pragma unroll
    for (int t = 0; t < 2; t++) {
        int gia = i0 + wr * 32 + t * 16 + r0;
#pragma unroll
        for (int j = 0; j < 8; j++) {
            int gj = j0 + wc * 64 + j * 8 + cp2;
            float v00 = acc[t][j][0], v01 = acc[t][j][1];
            float v10 = acc[t][j][2], v11 = acc[t][j][3];

            if (mode == MODE_COV) {
                float* dst = &g_covp[sK][mz][0];
                *(float2*)&dst[(long)gia * C_ + gj]       = make_float2(v00, v01);
                *(float2*)&dst[(long)(gia + 8) * C_ + gj] = make_float2(v10, v11);
                if (bx != by) {
                    dst[(long)gj * C_ + gia]           = v00;
                    dst[(long)(gj + 1) * C_ + gia]     = v01;
                    dst[(long)gj * C_ + gia + 8]       = v10;
                    dst[(long)(gj + 1) * C_ + gia + 8] = v11;
                }
            } else {
                float sm0 = g_mean[1][bz][gia], sm1 = g_mean[1][bz][gia + 8];
                float* o0 = outp + ((long)bz * C_ + gia) * N_ + gj;
                *(float2*)o0 = make_float2(v00 + sm0, v01 + sm0);
                float* o1 = outp + ((long)bz * C_ + gia + 8) * N_ + gj;
                *(float2*)o1 = make_float2(v10 + sm1, v11 + sm1);
            }
        }
    }
}

// ---------------- launch sequence (graph-capturable, deterministic) ----------------
extern "C" void kernel_launch(void* const* d_in, const int* in_sizes, int n_in,
                              void* d_out, int out_size)
{
    const float* content = (const float*)d_in[0];
    const float* style   = (const float*)d_in[1];
    float* out = (float*)d_out;

    cudaFuncSetAttribute(mma_kernel, cudaFuncAttributeMaxDynamicSharedMemorySize, SMEM_DYN);

    means_split_kernel<<<4096, 256>>>(content, style);
    transpose_kernel<<<dim3(N_ / 32, C_ / 32, B_), 256>>>(content);

    mma_kernel<<<dim3(4, 4, NMAT * KSPLIT), 256, SMEM_DYN>>>(MODE_COV, 0, nullptr);

    ns_persistent_kernel<<<PGRID, 256>>>();

    mma_kernel<<<dim3(N_ / 128, 4, B_), 256, SMEM_DYN>>>(MODE_APPLY, 0, out);
}

// round 13
// speedup vs baseline: 1.3306x; 1.3306x over previous
#include <cuda_runtime.h>
#include <cuda_bf16.h>
#include <math.h>
#include <stdint.h>

#define C_    512
#define N_    16384
#define B_    4
#define NMAT  8
#define EPS_  1e-5f
#define NS_ITERS 6
#define KSPLIT 8
#define KSEG  (N_ / KSPLIT)       // 2048

#define MODE_COV     0
#define MODE_G       1
#define MODE_YZ      2
#define MODE_COMBINE 3
#define MODE_APPLY   4

// SMEM: A tensors 128 x 40(pad) bf16 = 10240B each.
// Normal-B modes: B tensors also 128 x 40 = 10240B each  -> stage 40960B
// Trans-B (APPLY): B tensors 32 rows x 136(pad) bf16 = 8704B each -> stage 37888B
#define TEN_BYTES   10240
#define BT_TEN      8704
#define STAGE_BYTES 40960
#define SMEM_DYN    81920

// ---------------- device scratch (no allocations allowed) ----------------
__device__ float g_mean[2][B_][C_];                  // [0]=content, [1]=style
__device__ float g_cov[NMAT][C_ * C_];
__device__ float g_covp[KSPLIT][NMAT][C_ * C_];      // split-K raw partials
__device__ float g_s[NMAT], g_sinv[NMAT];
__device__ __nv_bfloat16 g_xh[2][B_][C_][N_];        // centered hi  [src][b][c][n]
__device__ __nv_bfloat16 g_xm[2][B_][C_][N_];        // centered mid
__device__ __nv_bfloat16 g_Yh[2][NMAT][C_ * C_], g_Ym[2][NMAT][C_ * C_];
__device__ __nv_bfloat16 g_Zh[2][NMAT][C_ * C_], g_Zm[2][NMAT][C_ * C_];
__device__ __nv_bfloat16 g_Gh[NMAT][C_ * C_], g_Gm[NMAT][C_ * C_];
__device__ __nv_bfloat16 g_Mh[B_][C_ * C_], g_Mm[B_][C_ * C_];

// ---------------- PTX helpers (all sm_80+ features only) ----------------
__device__ __forceinline__ uint32_t smem_u32(const void* p) {
    uint32_t a;
    asm("{ .reg .u64 t; cvta.to.shared.u64 t, %1; cvt.u32.u64 %0, t; }" : "=r"(a) : "l"(p));
    return a;
}
#define CP_ASYNC(dst, src) asm volatile("cp.async.cg.shared.global [%0], [%1], 16;" :: "r"(dst), "l"(src))
#define CP_COMMIT()        asm volatile("cp.async.commit_group;" ::: "memory")
#define CP_WAIT1()         asm volatile("cp.async.wait_group 1;" ::: "memory")
#define CP_WAIT0()         asm volatile("cp.async.wait_group 0;" ::: "memory")

__device__ __forceinline__ void ldsm4(uint32_t* r, uint32_t addr) {
    asm volatile("ldmatrix.sync.aligned.m8n8.x4.shared.b16 {%0,%1,%2,%3}, [%4];"
        : "=r"(r[0]), "=r"(r[1]), "=r"(r[2]), "=r"(r[3]) : "r"(addr));
}
__device__ __forceinline__ void ldsm4t(uint32_t* r, uint32_t addr) {
    asm volatile("ldmatrix.sync.aligned.m8n8.x4.trans.shared.b16 {%0,%1,%2,%3}, [%4];"
        : "=r"(r[0]), "=r"(r[1]), "=r"(r[2]), "=r"(r[3]) : "r"(addr));
}
__device__ __forceinline__ void mma16816(float* c, const uint32_t* a, const uint32_t* b) {
    asm volatile("mma.sync.aligned.m16n8k16.row.col.f32.bf16.bf16.f32 "
        "{%0,%1,%2,%3}, {%4,%5,%6,%7}, {%8,%9}, {%0,%1,%2,%3};"
        : "+f"(c[0]), "+f"(c[1]), "+f"(c[2]), "+f"(c[3])
        : "r"(a[0]), "r"(a[1]), "r"(a[2]), "r"(a[3]), "r"(b[0]), "r"(b[1]));
}
__device__ __forceinline__ void split2(float v, __nv_bfloat16& h, __nv_bfloat16& m) {
    h = __float2bfloat16(v);
    m = __float2bfloat16(v - __bfloat162float(h));
}

// ---------------- fused means + center + split (single read of inputs) ----------------
__global__ __launch_bounds__(256) void means_split_kernel(
    const float* __restrict__ content, const float* __restrict__ style)
{
    int idx = blockIdx.x;
    int src = idx >> 11, b = (idx >> 9) & 3, c = idx & 511;
    const float4* X4 = (const float4*)((src ? style : content) + (size_t)(b * C_ + c) * N_);

    float4 v[16];
    float sum = 0.f;
#pragma unroll
    for (int j = 0; j < 16; j++) {
        v[j] = X4[threadIdx.x + j * 256];
        sum += (v[j].x + v[j].y) + (v[j].z + v[j].w);
    }
    __shared__ float red[256];
    red[threadIdx.x] = sum;
    __syncthreads();
    for (int s = 128; s; s >>= 1) {
        if (threadIdx.x < s) red[threadIdx.x] += red[threadIdx.x + s];
        __syncthreads();
    }
    float mu = red[0] * (1.0f / N_);
    if (threadIdx.x == 0) g_mean[src][b][c] = mu;

    __nv_bfloat162* H = (__nv_bfloat162*)&g_xh[src][b][c][0];
    __nv_bfloat162* M = (__nv_bfloat162*)&g_xm[src][b][c][0];
#pragma unroll
    for (int j = 0; j < 16; j++) {
        int i = threadIdx.x + j * 256;
        __nv_bfloat16 h0, m0, h1, m1, h2, m2, h3, m3;
        split2(v[j].x - mu, h0, m0); split2(v[j].y - mu, h1, m1);
        split2(v[j].z - mu, h2, m2); split2(v[j].w - mu, h3, m3);
        __nv_bfloat162 a, b2;
        a.x = h0; a.y = h1; b2.x = h2; b2.y = h3;
        H[2 * i] = a; H[2 * i + 1] = b2;
        a.x = m0; a.y = m1; b2.x = m2; b2.y = m3;
        M[2 * i] = a; M[2 * i + 1] = b2;
    }
}

// fold split-K partials: cov = sum(partials)*inv + eps*I
__global__ __launch_bounds__(256) void cov_reduce_kernel()
{
    int i = blockIdx.x * 256 + threadIdx.x;   // 8 * 262144
    int m = i >> 18;
    int r = i & (C_ * C_ - 1);
    float v = 0.f;
#pragma unroll
    for (int s = 0; s < KSPLIT; s++) v += g_covp[s][m][r];
    v *= 1.0f / (float)(N_ - 1);
    if ((r >> 9) == (r & 511)) v += EPS_;
    g_cov[m][r] = v;
}

__global__ __launch_bounds__(256) void scale_kernel()
{
    int m = blockIdx.x;
    const float* covm = g_cov[m];
    float ss = 0.f;
    for (int i = threadIdx.x; i < C_ * C_; i += 256) {
        float v = covm[i];
        ss += v * v;
    }
    __shared__ float red[256];
    red[threadIdx.x] = ss;
    __syncthreads();
    for (int s = 128; s; s >>= 1) {
        if (threadIdx.x < s) red[threadIdx.x] += red[threadIdx.x + s];
        __syncthreads();
    }
    if (threadIdx.x == 0) {
        float sc = sqrtf(red[0]) * (1.0f / 2.5f);
        g_s[m] = sc;
        g_sinv[m] = 1.0f / sc;
    }
}

__global__ __launch_bounds__(256) void init_ns_kernel()
{
    int i = blockIdx.x * 256 + threadIdx.x;   // 8 * 262144
    int m = i >> 18;
    int r = i & (C_ * C_ - 1);
    float v = g_cov[m][r] * g_sinv[m];
    __nv_bfloat16 h, mm;
    split2(v, h, mm);
    g_Yh[0][m][r] = h;
    g_Ym[0][m][r] = mm;
    bool dg = ((r >> 9) == (r & 511));
    g_Zh[0][m][r] = __float2bfloat16(dg ? 1.0f : 0.0f);
    g_Zm[0][m][r] = __float2bfloat16(0.0f);
}

// ---------------- cp.async stage fill ----------------
// normal: A,B both [row][k] 128 x 32, stride-40 pad
__device__ __forceinline__ void fill_stage(uint32_t sbase,
    const __nv_bfloat16* ah, const __nv_bfloat16* am,
    const __nv_bfloat16* bh, const __nv_bfloat16* bm,
    long sA, long sB, int tid)
{
#pragma unroll
    for (int t = tid; t < 512; t += 256) {
        int row = t >> 2, q = (t & 3) * 8;
        uint32_t d = sbase + (uint32_t)(row * 40 + q) * 2;
        long oa = (long)row * sA + q, ob = (long)row * sB + q;
        CP_ASYNC(d,                 ah + oa);
        CP_ASYNC(d + TEN_BYTES,     am + oa);
        CP_ASYNC(d + 2 * TEN_BYTES, bh + ob);
        CP_ASYNC(d + 3 * TEN_BYTES, bm + ob);
    }
}

// trans-B (APPLY): A [i][k] 128 x 32 stride-40; B natural [k][n] 32 x 128, stride-136 pad
__device__ __forceinline__ void fill_stage_t(uint32_t sbase,
    const __nv_bfloat16* ah, const __nv_bfloat16* am,
    const __nv_bfloat16* bh, const __nv_bfloat16* bm, int tid)
{
    // A: 512 chunks (128 rows x 4 quads)
#pragma unroll
    for (int t = tid; t < 512; t += 256) {
        int row = t >> 2, q = (t & 3) * 8;
        uint32_t d = sbase + (uint32_t)(row * 40 + q) * 2;
        long oa = (long)row * C_ + q;
        CP_ASYNC(d,             ah + oa);
        CP_ASYNC(d + TEN_BYTES, am + oa);
    }
    // B: 512 chunks (32 k-rows x 16 n-chunks of 8)
#pragma unroll
    for (int t = tid; t < 512; t += 256) {
        int row = t >> 4, q = (t & 15) * 8;
        uint32_t d = sbase + 2 * TEN_BYTES + (uint32_t)(row * 136 + q) * 2;
        long ob = (long)row * N_ + q;
        CP_ASYNC(d,          bh + ob);
        CP_ASYNC(d + BT_TEN, bm + ob);
    }
}

// ---------------- 128-tile warp-MMA kernel: D(128x128) = A * B^T, bf16 hi/mid 3-pass ----------------
__global__ __launch_bounds__(256, 2) void mma_kernel(int mode, int flag, float* __restrict__ outp)
{
    int bx = blockIdx.x, by = blockIdx.y, bz = blockIdx.z;
    bool sym = (mode <= MODE_YZ);
    if (sym && by > bx) return;               // upper-triangle tiles only; mirror in epilogue
    int i0 = by * 128, j0 = bx * 128;
    bool btrans = (mode == MODE_APPLY);

    const __nv_bfloat16 *Ah, *Am, *Bh, *Bm;
    long sA, sB;
    int K;
    int mz = bz, sK = 0;
    if (mode == MODE_COV) {
        mz = bz & 7; sK = bz >> 3;            // mat, K-split
        int src = mz >> 2, b = mz & 3;
        long ks = (long)sK * KSEG;
        Ah = &g_xh[src][b][i0][0] + ks; Am = &g_xm[src][b][i0][0] + ks;
        Bh = &g_xh[src][b][j0][0] + ks; Bm = &g_xm[src][b][j0][0] + ks;
        sA = sB = N_; K = KSEG;
    } else if (mode == MODE_G) {              // G = (3I - Z*Y)/2 ; D = Z * Y^T (Y sym)
        Ah = g_Zh[flag][bz] + (long)i0 * C_; Am = g_Zm[flag][bz] + (long)i0 * C_;
        Bh = g_Yh[flag][bz] + (long)j0 * C_; Bm = g_Ym[flag][bz] + (long)j0 * C_;
        sA = sB = C_; K = C_;
    } else if (mode == MODE_YZ) {
        int m = bz & 7;
        sA = sB = C_; K = C_;
        if (bz < 8) {                          // Ynew = Y * G   (G sym)
            Ah = g_Yh[flag][m] + (long)i0 * C_; Am = g_Ym[flag][m] + (long)i0 * C_;
            Bh = g_Gh[m] + (long)j0 * C_;       Bm = g_Gm[m] + (long)j0 * C_;
        } else {                               // Znew = G * Z   (Z sym)
            Ah = g_Gh[m] + (long)i0 * C_;       Am = g_Gm[m] + (long)i0 * C_;
            Bh = g_Zh[flag][m] + (long)j0 * C_; Bm = g_Zm[flag][m] + (long)j0 * C_;
        }
    } else if (mode == MODE_COMBINE) {         // M = alpha * Y_style * Z_content^T
        Ah = g_Yh[0][4 + bz] + (long)i0 * C_; Am = g_Ym[0][4 + bz] + (long)i0 * C_;
        Bh = g_Zh[0][bz] + (long)j0 * C_;     Bm = g_Zm[0][bz] + (long)j0 * C_;
        sA = sB = C_; K = C_;
    } else {                                   // APPLY: out = M * Xc (+ s_mean); B natural [k][n]
        Ah = g_Mh[bz] + (long)i0 * C_;       Am = g_Mm[bz] + (long)i0 * C_;
        Bh = &g_xh[0][bz][0][j0];            Bm = &g_xm[0][bz][0][j0];
        sA = C_; sB = N_; K = C_;
    }

    extern __shared__ char dsm[];
    uint32_t sb = smem_u32(dsm);
    int tid = threadIdx.x, wid = tid >> 5, l = tid & 31;
    int wr = wid & 3, wc = wid >> 2;            // warp grid 4 (m) x 2 (n)

    // lane-invariant ldmatrix offsets (bytes, kk=0)
    uint32_t aoff[2], boff[4];
#pragma unroll
    for (int t = 0; t < 2; t++)
        aoff[t] = (uint32_t)(((wr * 32 + t * 16 + (l & 15)) * 40 + ((l >> 4) << 3)) * 2);
    int g = l >> 3;
    if (!btrans) {
#pragma unroll
        for (int jp = 0; jp < 4; jp++) {
            int row = wc * 64 + jp * 16 + (l & 7) + ((g >= 2) ? 8 : 0);
            boff[jp] = (uint32_t)((row * 40 + ((g & 1) << 3)) * 2);
        }
    } else {
        // trans ldsm from [k][n]: tile order g0:(k0-7,n0-7) g1:(k8-15,n0-7) g2:(k0-7,n8-15) g3:(k8-15,n8-15)
        int krow = (l & 7) + ((g & 1) ? 8 : 0);
#pragma unroll
        for (int jp = 0; jp < 4; jp++) {
            int ncol = wc * 64 + jp * 16 + ((g >= 2) ? 8 : 0);
            boff[jp] = (uint32_t)((krow * 136 + ncol) * 2);
        }
    }
    uint32_t bkof = btrans ? (uint32_t)(16 * 136 * 2) : 32u;  // kk -> +16 k

    float acc[2][8][4];
#pragma unroll
    for (int t = 0; t < 2; t++)
#pragma unroll
        for (int j = 0; j < 8; j++)
#pragma unroll
            for (int q = 0; q < 4; q++) acc[t][j][q] = 0.f;

    int nch = K / 32;
    if (!btrans) {
        fill_stage(sb, Ah, Am, Bh, Bm, sA, sB, tid); CP_COMMIT();
        fill_stage(sb + STAGE_BYTES, Ah + 32, Am + 32, Bh + 32, Bm + 32, sA, sB, tid); CP_COMMIT();
    } else {
        fill_stage_t(sb, Ah, Am, Bh, Bm, tid); CP_COMMIT();
        fill_stage_t(sb + STAGE_BYTES, Ah + 32, Am + 32, Bh + 32 * N_, Bm + 32 * N_, tid); CP_COMMIT();
    }

    for (int c = 0; c < nch; c++) {
        if (c + 1 < nch) CP_WAIT1(); else CP_WAIT0();
        __syncthreads();
        uint32_t stb = sb + (uint32_t)(c & 1) * STAGE_BYTES;
#pragma unroll
        for (int kk = 0; kk < 2; kk++) {
            uint32_t kofA = (uint32_t)kk * 32;
            uint32_t kofB = (uint32_t)kk * bkof;
            uint32_t fa[2][4], fm[2][4];
            ldsm4(fa[0], stb + aoff[0] + kofA);
            ldsm4(fa[1], stb + aoff[1] + kofA);
            ldsm4(fm[0], stb + TEN_BYTES + aoff[0] + kofA);
            ldsm4(fm[1], stb + TEN_BYTES + aoff[1] + kofA);
#pragma unroll
            for (int jp = 0; jp < 4; jp++) {
                uint32_t bh[4], bm2[4];
                if (!btrans) {
                    ldsm4(bh,  stb + 2 * TEN_BYTES + boff[jp] + kofB);
                    ldsm4(bm2, stb + 3 * TEN_BYTES + boff[jp] + kofB);
                } else {
                    ldsm4t(bh,  stb + 2 * TEN_BYTES + boff[jp] + kofB);
                    ldsm4t(bm2, stb + 2 * TEN_BYTES + BT_TEN + boff[jp] + kofB);
                }
                // pass-outer ordering: 4 independent accumulators between RAW reuses
                mma16816(acc[0][2 * jp],     fa[0], &bh[0]);
                mma16816(acc[0][2 * jp + 1], fa[0], &bh[2]);
                mma16816(acc[1][2 * jp],     fa[1], &bh[0]);
                mma16816(acc[1][2 * jp + 1], fa[1], &bh[2]);
                mma16816(acc[0][2 * jp],     fa[0], &bm2[0]);
                mma16816(acc[0][2 * jp + 1], fa[0], &bm2[2]);
                mma16816(acc[1][2 * jp],     fa[1], &bm2[0]);
                mma16816(acc[1][2 * jp + 1], fa[1], &bm2[2]);
                mma16816(acc[0][2 * jp],     fm[0], &bh[0]);
                mma16816(acc[0][2 * jp + 1], fm[0], &bh[2]);
                mma16816(acc[1][2 * jp],     fm[1], &bh[0]);
                mma16816(acc[1][2 * jp + 1], fm[1], &bh[2]);
            }
        }
        __syncthreads();
        if (c + 2 < nch) {
            long ko = (long)(c + 2) * 32;
            uint32_t dstb = sb + (uint32_t)(c & 1) * STAGE_BYTES;
            if (!btrans)
                fill_stage(dstb, Ah + ko, Am + ko, Bh + ko, Bm + ko, sA, sB, tid);
            else
                fill_stage_t(dstb, Ah + ko, Am + ko, Bh + ko * N_, Bm + ko * N_, tid);
            CP_COMMIT();
        }
    }

    // ---------------- epilogue straight from registers ----------------
    int r0 = l >> 2, cp2 = (l & 3) * 2;
    float alpha = (mode == MODE_COMBINE) ? sqrtf(g_s[4 + bz] / g_s[bz]) : 1.0f;

#pragma unroll
    for (int t = 0; t < 2; t++) {
        int gia = i0 + wr * 32 + t * 16 + r0;     // rows gia, gia+8
#pragma unroll
        for (int j = 0; j < 8; j++) {
            int gj = j0 + wc * 64 + j * 8 + cp2;  // cols gj, gj+1
            float v00 = acc[t][j][0], v01 = acc[t][j][1];
            float v10 = acc[t][j][2], v11 = acc[t][j][3];

            if (mode == MODE_COV) {
                float* dst = &g_covp[sK][mz][0];   // raw partial sums
                *(float2*)&dst[(long)gia * C_ + gj]       = make_float2(v00, v01);
                *(float2*)&dst[(long)(gia + 8) * C_ + gj] = make_float2(v10, v11);
                if (bx != by) {
                    dst[(long)gj * C_ + gia]           = v00;
                    dst[(long)(gj + 1) * C_ + gia]     = v01;
                    dst[(long)gj * C_ + gia + 8]       = v10;
                    dst[(long)(gj + 1) * C_ + gia + 8] = v11;
                }
            } else if (mode == MODE_APPLY) {
                float sm0 = g_mean[1][bz][gia], sm1 = g_mean[1][bz][gia + 8];
                float* o0 = outp + ((long)bz * C_ + gia) * N_ + gj;
                *(float2*)o0 = make_float2(v00 + sm0, v01 + sm0);
                float* o1 = outp + ((long)bz * C_ + gia + 8) * N_ + gj;
                *(float2*)o1 = make_float2(v10 + sm1, v11 + sm1);
            } else {
                __nv_bfloat16 *dh, *dm;
                if (mode == MODE_G) {
                    dh = g_Gh[bz]; dm = g_Gm[bz];
                    v00 = -0.5f * v00 + ((gj     == gia)     ? 1.5f : 0.f);
                    v01 = -0.5f * v01 + ((gj + 1 == gia)     ? 1.5f : 0.f);
                    v10 = -0.5f * v10 + ((gj     == gia + 8) ? 1.5f : 0.f);
                    v11 = -0.5f * v11 + ((gj + 1 == gia + 8) ? 1.5f : 0.f);
                } else if (mode == MODE_YZ) {
                    int m = bz & 7;
                    if (bz < 8) { dh = g_Yh[flag ^ 1][m]; dm = g_Ym[flag ^ 1][m]; }
                    else        { dh = g_Zh[flag ^ 1][m]; dm = g_Zm[flag ^ 1][m]; }
                } else {
                    dh = g_Mh[bz]; dm = g_Mm[bz];
                    v00 *= alpha; v01 *= alpha; v10 *= alpha; v11 *= alpha;
                }
                __nv_bfloat16 h00, m00, h01, m01, h10, m10, h11, m11;
                split2(v00, h00, m00); split2(v01, h01, m01);
                split2(v10, h10, m10); split2(v11, h11, m11);
                __nv_bfloat162 ph0; ph0.x = h00; ph0.y = h01;
                __nv_bfloat162 pm0; pm0.x = m00; pm0.y = m01;
                __nv_bfloat162 ph1; ph1.x = h10; ph1.y = h11;
                __nv_bfloat162 pm1; pm1.x = m10; pm1.y = m11;
                *(__nv_bfloat162*)&dh[(long)gia * C_ + gj]       = ph0;
                *(__nv_bfloat162*)&dm[(long)gia * C_ + gj]       = pm0;
                *(__nv_bfloat162*)&dh[(long)(gia + 8) * C_ + gj] = ph1;
                *(__nv_bfloat162*)&dm[(long)(gia + 8) * C_ + gj] = pm1;
                if (sym && bx != by) {
                    dh[(long)gj * C_ + gia] = h00;           dm[(long)gj * C_ + gia] = m00;
                    dh[(long)(gj + 1) * C_ + gia] = h01;     dm[(long)(gj + 1) * C_ + gia] = m01;
                    dh[(long)gj * C_ + gia + 8] = h10;       dm[(long)gj * C_ + gia + 8] = m10;
                    dh[(long)(gj + 1) * C_ + gia + 8] = h11; dm[(long)(gj + 1) * C_ + gia + 8] = m11;
                }
            }
        }
    }
}

// ---------------- launch sequence (graph-capturable, deterministic) ----------------
extern "C" void kernel_launch(void* const* d_in, const int* in_sizes, int n_in,
                              void* d_out, int out_size)
{
    const float* content = (const float*)d_in[0];
    const float* style   = (const float*)d_in[1];
    float* out = (float*)d_out;

    cudaFuncSetAttribute(mma_kernel, cudaFuncAttributeMaxDynamicSharedMemorySize, SMEM_DYN);

    means_split_kernel<<<4096, 256>>>(content, style);

    mma_kernel<<<dim3(4, 4, NMAT * KSPLIT), 256, SMEM_DYN>>>(MODE_COV, 0, nullptr);
    cov_reduce_kernel<<<NMAT * C_ * C_ / 256, 256>>>();
    scale_kernel<<<NMAT, 256>>>();
    init_ns_kernel<<<NMAT * C_ * C_ / 256, 256>>>();

    for (int it = 0; it < NS_ITERS; it++) {
        mma_kernel<<<dim3(4, 4, NMAT), 256, SMEM_DYN>>>(MODE_G, it & 1, nullptr);
        mma_kernel<<<dim3(4, 4, NMAT * 2), 256, SMEM_DYN>>>(MODE_YZ, it & 1, nullptr);
    }

    // NS_ITERS=6 -> final Y/Z live in buffer [0]
    mma_kernel<<<dim3(4, 4, B_), 256, SMEM_DYN>>>(MODE_COMBINE, 0, nullptr);
    mma_kernel<<<dim3(N_ / 128, 4, B_), 256, SMEM_DYN>>>(MODE_APPLY, 0, out);
}

// round 14
// speedup vs baseline: 1.5495x; 1.1645x over previous
#include <cuda_runtime.h>
#include <cuda_bf16.h>
#include <math.h>
#include <stdint.h>

#define C_    512
#define N_    16384
#define B_    4
#define NMAT  8
#define EPS_  1e-5f
#define NS_ITERS 4                // with tight spectral scaling (divisor 16), eps4 ~ 2e-6
#define SCALE_DIV 16.0f
#define KSPLIT 8
#define KSEG  (N_ / KSPLIT)       // 2048

#define MODE_COV     0
#define MODE_G       1
#define MODE_YZ      2
#define MODE_COMBINE 3
#define MODE_APPLY   4

// SMEM: A tensors 128 x 40(pad) bf16 = 10240B each.
// Normal-B modes: B tensors also 128 x 40 = 10240B each  -> stage 40960B
// Trans-B (APPLY): B tensors 32 rows x 136(pad) bf16 = 8704B each -> stage 37888B
#define TEN_BYTES   10240
#define BT_TEN      8704
#define STAGE_BYTES 40960
#define SMEM_DYN    81920

// ---------------- device scratch (no allocations allowed) ----------------
__device__ float g_mean[2][B_][C_];                  // [0]=content, [1]=style
__device__ float g_cov[NMAT][C_ * C_];
__device__ float g_covp[KSPLIT][NMAT][C_ * C_];      // split-K raw partials
__device__ float g_ssp[NMAT * 1024];                 // per-block Frobenius partials
__device__ float g_s[NMAT], g_sinv[NMAT];
__device__ __nv_bfloat16 g_xh[2][B_][C_][N_];        // centered hi  [src][b][c][n]
__device__ __nv_bfloat16 g_xm[2][B_][C_][N_];        // centered mid
__device__ __nv_bfloat16 g_Yh[2][NMAT][C_ * C_], g_Ym[2][NMAT][C_ * C_];
__device__ __nv_bfloat16 g_Zh[2][NMAT][C_ * C_], g_Zm[2][NMAT][C_ * C_];
__device__ __nv_bfloat16 g_Gh[NMAT][C_ * C_], g_Gm[NMAT][C_ * C_];
__device__ __nv_bfloat16 g_Mh[B_][C_ * C_], g_Mm[B_][C_ * C_];

// ---------------- PTX helpers (all sm_80+ features only) ----------------
__device__ __forceinline__ uint32_t smem_u32(const void* p) {
    uint32_t a;
    asm("{ .reg .u64 t; cvta.to.shared.u64 t, %1; cvt.u32.u64 %0, t; }" : "=r"(a) : "l"(p));
    return a;
}
#define CP_ASYNC(dst, src) asm volatile("cp.async.cg.shared.global [%0], [%1], 16;" :: "r"(dst), "l"(src))
#define CP_COMMIT()        asm volatile("cp.async.commit_group;" ::: "memory")
#define CP_WAIT1()         asm volatile("cp.async.wait_group 1;" ::: "memory")
#define CP_WAIT0()         asm volatile("cp.async.wait_group 0;" ::: "memory")

__device__ __forceinline__ void ldsm4(uint32_t* r, uint32_t addr) {
    asm volatile("ldmatrix.sync.aligned.m8n8.x4.shared.b16 {%0,%1,%2,%3}, [%4];"
        : "=r"(r[0]), "=r"(r[1]), "=r"(r[2]), "=r"(r[3]) : "r"(addr));
}
__device__ __forceinline__ void ldsm4t(uint32_t* r, uint32_t addr) {
    asm volatile("ldmatrix.sync.aligned.m8n8.x4.trans.shared.b16 {%0,%1,%2,%3}, [%4];"
        : "=r"(r[0]), "=r"(r[1]), "=r"(r[2]), "=r"(r[3]) : "r"(addr));
}
__device__ __forceinline__ void mma16816(float* c, const uint32_t* a, const uint32_t* b) {
    asm volatile("mma.sync.aligned.m16n8k16.row.col.f32.bf16.bf16.f32 "
        "{%0,%1,%2,%3}, {%4,%5,%6,%7}, {%8,%9}, {%0,%1,%2,%3};"
        : "+f"(c[0]), "+f"(c[1]), "+f"(c[2]), "+f"(c[3])
        : "r"(a[0]), "r"(a[1]), "r"(a[2]), "r"(a[3]), "r"(b[0]), "r"(b[1]));
}
__device__ __forceinline__ void split2(float v, __nv_bfloat16& h, __nv_bfloat16& m) {
    h = __float2bfloat16(v);
    m = __float2bfloat16(v - __bfloat162float(h));
}

// ---------------- fused means + center + split (single read of inputs) ----------------
__global__ __launch_bounds__(256) void means_split_kernel(
    const float* __restrict__ content, const float* __restrict__ style)
{
    int idx = blockIdx.x;
    int src = idx >> 11, b = (idx >> 9) & 3, c = idx & 511;
    const float4* X4 = (const float4*)((src ? style : content) + (size_t)(b * C_ + c) * N_);

    float4 v[16];
    float sum = 0.f;
#pragma unroll
    for (int j = 0; j < 16; j++) {
        v[j] = X4[threadIdx.x + j * 256];
        sum += (v[j].x + v[j].y) + (v[j].z + v[j].w);
    }
    __shared__ float red[256];
    red[threadIdx.x] = sum;
    __syncthreads();
    for (int s = 128; s; s >>= 1) {
        if (threadIdx.x < s) red[threadIdx.x] += red[threadIdx.x + s];
        __syncthreads();
    }
    float mu = red[0] * (1.0f / N_);
    if (threadIdx.x == 0) g_mean[src][b][c] = mu;

    __nv_bfloat162* H = (__nv_bfloat162*)&g_xh[src][b][c][0];
    __nv_bfloat162* M = (__nv_bfloat162*)&g_xm[src][b][c][0];
#pragma unroll
    for (int j = 0; j < 16; j++) {
        int i = threadIdx.x + j * 256;
        __nv_bfloat16 h0, m0, h1, m1, h2, m2, h3, m3;
        split2(v[j].x - mu, h0, m0); split2(v[j].y - mu, h1, m1);
        split2(v[j].z - mu, h2, m2); split2(v[j].w - mu, h3, m3);
        __nv_bfloat162 a, b2;
        a.x = h0; a.y = h1; b2.x = h2; b2.y = h3;
        H[2 * i] = a; H[2 * i + 1] = b2;
        a.x = m0; a.y = m1; b2.x = m2; b2.y = m3;
        M[2 * i] = a; M[2 * i + 1] = b2;
    }
}

// fold split-K partials: cov = sum(partials)*inv + eps*I ; also per-block Frobenius partials
__global__ __launch_bounds__(256) void cov_reduce_kernel()
{
    int i = blockIdx.x * 256 + threadIdx.x;   // 8 * 262144
    int m = i >> 18;
    int r = i & (C_ * C_ - 1);
    float v = 0.f;
#pragma unroll
    for (int s = 0; s < KSPLIT; s++) v += g_covp[s][m][r];
    v *= 1.0f / (float)(N_ - 1);
    if ((r >> 9) == (r & 511)) v += EPS_;
    g_cov[m][r] = v;

    // deterministic per-block Frobenius partial (block spans one matrix only)
    __shared__ float red[256];
    red[threadIdx.x] = v * v;
    __syncthreads();
    for (int s = 128; s; s >>= 1) {
        if (threadIdx.x < s) red[threadIdx.x] += red[threadIdx.x + s];
        __syncthreads();
    }
    if (threadIdx.x == 0) g_ssp[blockIdx.x] = red[0];
}

// finalize spectral scale: warp w reduces matrix w's 1024 partials (deterministic order)
__global__ __launch_bounds__(256) void scale_finalize_kernel()
{
    int w = threadIdx.x >> 5, l = threadIdx.x & 31;
    float s = 0.f;
#pragma unroll
    for (int j = 0; j < 32; j++) s += g_ssp[w * 1024 + j * 32 + l];
#pragma unroll
    for (int o = 16; o; o >>= 1) s += __shfl_xor_sync(0xFFFFFFFF, s, o);
    if (l == 0) {
        float sc = sqrtf(s) * (1.0f / SCALE_DIV);
        g_s[w] = sc;
        g_sinv[w] = 1.0f / sc;
    }
}

__global__ __launch_bounds__(256) void init_ns_kernel()
{
    int i = blockIdx.x * 256 + threadIdx.x;   // 8 * 262144
    int m = i >> 18;
    int r = i & (C_ * C_ - 1);
    float v = g_cov[m][r] * g_sinv[m];
    __nv_bfloat16 h, mm;
    split2(v, h, mm);
    g_Yh[0][m][r] = h;
    g_Ym[0][m][r] = mm;
    bool dg = ((r >> 9) == (r & 511));
    g_Zh[0][m][r] = __float2bfloat16(dg ? 1.0f : 0.0f);
    g_Zm[0][m][r] = __float2bfloat16(0.0f);
}

// ---------------- cp.async stage fill ----------------
// normal: A,B both [row][k] 128 x 32, stride-40 pad
__device__ __forceinline__ void fill_stage(uint32_t sbase,
    const __nv_bfloat16* ah, const __nv_bfloat16* am,
    const __nv_bfloat16* bh, const __nv_bfloat16* bm,
    long sA, long sB, int tid)
{
#pragma unroll
    for (int t = tid; t < 512; t += 256) {
        int row = t >> 2, q = (t & 3) * 8;
        uint32_t d = sbase + (uint32_t)(row * 40 + q) * 2;
        long oa = (long)row * sA + q, ob = (long)row * sB + q;
        CP_ASYNC(d,                 ah + oa);
        CP_ASYNC(d + TEN_BYTES,     am + oa);
        CP_ASYNC(d + 2 * TEN_BYTES, bh + ob);
        CP_ASYNC(d + 3 * TEN_BYTES, bm + ob);
    }
}

// trans-B (APPLY): A [i][k] 128 x 32 stride-40; B natural [k][n] 32 x 128, stride-136 pad
__device__ __forceinline__ void fill_stage_t(uint32_t sbase,
    const __nv_bfloat16* ah, const __nv_bfloat16* am,
    const __nv_bfloat16* bh, const __nv_bfloat16* bm, int tid)
{
#pragma unroll
    for (int t = tid; t < 512; t += 256) {
        int row = t >> 2, q = (t & 3) * 8;
        uint32_t d = sbase + (uint32_t)(row * 40 + q) * 2;
        long oa = (long)row * C_ + q;
        CP_ASYNC(d,             ah + oa);
        CP_ASYNC(d + TEN_BYTES, am + oa);
    }
#pragma unroll
    for (int t = tid; t < 512; t += 256) {
        int row = t >> 4, q = (t & 15) * 8;
        uint32_t d = sbase + 2 * TEN_BYTES + (uint32_t)(row * 136 + q) * 2;
        long ob = (long)row * N_ + q;
        CP_ASYNC(d,          bh + ob);
        CP_ASYNC(d + BT_TEN, bm + ob);
    }
}

// ---------------- 128-tile warp-MMA kernel: D(128x128) = A * B^T, bf16 hi/mid 3-pass ----------------
__global__ __launch_bounds__(256, 2) void mma_kernel(int mode, int flag, float* __restrict__ outp)
{
    int bx = blockIdx.x, by = blockIdx.y, bz = blockIdx.z;
    bool sym = (mode <= MODE_YZ);
    if (sym && by > bx) return;               // upper-triangle tiles only; mirror in epilogue
    int i0 = by * 128, j0 = bx * 128;
    bool btrans = (mode == MODE_APPLY);

    const __nv_bfloat16 *Ah, *Am, *Bh, *Bm;
    long sA, sB;
    int K;
    int mz = bz, sK = 0;
    if (mode == MODE_COV) {
        mz = bz & 7; sK = bz >> 3;            // mat, K-split
        int src = mz >> 2, b = mz & 3;
        long ks = (long)sK * KSEG;
        Ah = &g_xh[src][b][i0][0] + ks; Am = &g_xm[src][b][i0][0] + ks;
        Bh = &g_xh[src][b][j0][0] + ks; Bm = &g_xm[src][b][j0][0] + ks;
        sA = sB = N_; K = KSEG;
    } else if (mode == MODE_G) {              // G = (3I - Z*Y)/2 ; D = Z * Y^T (Y sym)
        Ah = g_Zh[flag][bz] + (long)i0 * C_; Am = g_Zm[flag][bz] + (long)i0 * C_;
        Bh = g_Yh[flag][bz] + (long)j0 * C_; Bm = g_Ym[flag][bz] + (long)j0 * C_;
        sA = sB = C_; K = C_;
    } else if (mode == MODE_YZ) {
        int m = bz & 7;
        sA = sB = C_; K = C_;
        if (bz < 8) {                          // Ynew = Y * G   (G sym)
            Ah = g_Yh[flag][m] + (long)i0 * C_; Am = g_Ym[flag][m] + (long)i0 * C_;
            Bh = g_Gh[m] + (long)j0 * C_;       Bm = g_Gm[m] + (long)j0 * C_;
        } else {                               // Znew = G * Z   (Z sym)
            Ah = g_Gh[m] + (long)i0 * C_;       Am = g_Gm[m] + (long)i0 * C_;
            Bh = g_Zh[flag][m] + (long)j0 * C_; Bm = g_Zm[flag][m] + (long)j0 * C_;
        }
    } else if (mode == MODE_COMBINE) {         // M = alpha * Y_style * Z_content^T
        Ah = g_Yh[0][4 + bz] + (long)i0 * C_; Am = g_Ym[0][4 + bz] + (long)i0 * C_;
        Bh = g_Zh[0][bz] + (long)j0 * C_;     Bm = g_Zm[0][bz] + (long)j0 * C_;
        sA = sB = C_; K = C_;
    } else {                                   // APPLY: out = M * Xc (+ s_mean); B natural [k][n]
        Ah = g_Mh[bz] + (long)i0 * C_;       Am = g_Mm[bz] + (long)i0 * C_;
        Bh = &g_xh[0][bz][0][j0];            Bm = &g_xm[0][bz][0][j0];
        sA = C_; sB = N_; K = C_;
    }

    extern __shared__ char dsm[];
    uint32_t sb = smem_u32(dsm);
    int tid = threadIdx.x, wid = tid >> 5, l = tid & 31;
    int wr = wid & 3, wc = wid >> 2;            // warp grid 4 (m) x 2 (n)

    // lane-invariant ldmatrix offsets (bytes, kk=0)
    uint32_t aoff[2], boff[4];
#pragma unroll
    for (int t = 0; t < 2; t++)
        aoff[t] = (uint32_t)(((wr * 32 + t * 16 + (l & 15)) * 40 + ((l >> 4) << 3)) * 2);
    int g = l >> 3;
    if (!btrans) {
#pragma unroll
        for (int jp = 0; jp < 4; jp++) {
            int row = wc * 64 + jp * 16 + (l & 7) + ((g >= 2) ? 8 : 0);
            boff[jp] = (uint32_t)((row * 40 + ((g & 1) << 3)) * 2);
        }
    } else {
        // trans ldsm from [k][n]: g0:(k0-7,n0-7) g1:(k8-15,n0-7) g2:(k0-7,n8-15) g3:(k8-15,n8-15)
        int krow = (l & 7) + ((g & 1) ? 8 : 0);
#pragma unroll
        for (int jp = 0; jp < 4; jp++) {
            int ncol = wc * 64 + jp * 16 + ((g >= 2) ? 8 : 0);
            boff[jp] = (uint32_t)((krow * 136 + ncol) * 2);
        }
    }
    uint32_t bkof = btrans ? (uint32_t)(16 * 136 * 2) : 32u;  // kk -> +16 k

    float acc[2][8][4];
#pragma unroll
    for (int t = 0; t < 2; t++)
#pragma unroll
        for (int j = 0; j < 8; j++)
#pragma unroll
            for (int q = 0; q < 4; q++) acc[t][j][q] = 0.f;

    int nch = K / 32;
    if (!btrans) {
        fill_stage(sb, Ah, Am, Bh, Bm, sA, sB, tid); CP_COMMIT();
        fill_stage(sb + STAGE_BYTES, Ah + 32, Am + 32, Bh + 32, Bm + 32, sA, sB, tid); CP_COMMIT();
    } else {
        fill_stage_t(sb, Ah, Am, Bh, Bm, tid); CP_COMMIT();
        fill_stage_t(sb + STAGE_BYTES, Ah + 32, Am + 32, Bh + 32 * N_, Bm + 32 * N_, tid); CP_COMMIT();
    }

    for (int c = 0; c < nch; c++) {
        if (c + 1 < nch) CP_WAIT1(); else CP_WAIT0();
        __syncthreads();
        uint32_t stb = sb + (uint32_t)(c & 1) * STAGE_BYTES;
#pragma unroll
        for (int kk = 0; kk < 2; kk++) {
            uint32_t kofA = (uint32_t)kk * 32;
            uint32_t kofB = (uint32_t)kk * bkof;
            uint32_t fa[2][4], fm[2][4];
            ldsm4(fa[0], stb + aoff[0] + kofA);
            ldsm4(fa[1], stb + aoff[1] + kofA);
            ldsm4(fm[0], stb + TEN_BYTES + aoff[0] + kofA);
            ldsm4(fm[1], stb + TEN_BYTES + aoff[1] + kofA);
#pragma unroll
            for (int jp = 0; jp < 4; jp++) {
                uint32_t bh[4], bm2[4];
                if (!btrans) {
                    ldsm4(bh,  stb + 2 * TEN_BYTES + boff[jp] + kofB);
                    ldsm4(bm2, stb + 3 * TEN_BYTES + boff[jp] + kofB);
                } else {
                    ldsm4t(bh,  stb + 2 * TEN_BYTES + boff[jp] + kofB);
                    ldsm4t(bm2, stb + 2 * TEN_BYTES + BT_TEN + boff[jp] + kofB);
                }
                // pass-outer ordering: 4 independent accumulators between RAW reuses
                mma16816(acc[0][2 * jp],     fa[0], &bh[0]);
                mma16816(acc[0][2 * jp + 1], fa[0], &bh[2]);
                mma16816(acc[1][2 * jp],     fa[1], &bh[0]);
                mma16816(acc[1][2 * jp + 1], fa[1], &bh[2]);
                mma16816(acc[0][2 * jp],     fa[0], &bm2[0]);
                mma16816(acc[0][2 * jp + 1], fa[0], &bm2[2]);
                mma16816(acc[1][2 * jp],     fa[1], &bm2[0]);
                mma16816(acc[1][2 * jp + 1], fa[1], &bm2[2]);
                mma16816(acc[0][2 * jp],     fm[0], &bh[0]);
                mma16816(acc[0][2 * jp + 1], fm[0], &bh[2]);
                mma16816(acc[1][2 * jp],     fm[1], &bh[0]);
                mma16816(acc[1][2 * jp + 1], fm[1], &bh[2]);
            }
        }
        __syncthreads();
        if (c + 2 < nch) {
            long ko = (long)(c + 2) * 32;
            uint32_t dstb = sb + (uint32_t)(c & 1) * STAGE_BYTES;
            if (!btrans)
                fill_stage(dstb, Ah + ko, Am + ko, Bh + ko, Bm + ko, sA, sB, tid);
            else
                fill_stage_t(dstb, Ah + ko, Am + ko, Bh + ko * N_, Bm + ko * N_, tid);
            CP_COMMIT();
        }
    }

    // ---------------- epilogue straight from registers ----------------
    int r0 = l >> 2, cp2 = (l & 3) * 2;
    float alpha = (mode == MODE_COMBINE) ? sqrtf(g_s[4 + bz] / g_s[bz]) : 1.0f;

#pragma unroll
    for (int t = 0; t < 2; t++) {
        int gia = i0 + wr * 32 + t * 16 + r0;     // rows gia, gia+8
#pragma unroll
        for (int j = 0; j < 8; j++) {
            int gj = j0 + wc * 64 + j * 8 + cp2;  // cols gj, gj+1
            float v00 = acc[t][j][0], v01 = acc[t][j][1];
            float v10 = acc[t][j][2], v11 = acc[t][j][3];

            if (mode == MODE_COV) {
                float* dst = &g_covp[sK][mz][0];   // raw partial sums
                *(float2*)&dst[(long)gia * C_ + gj]       = make_float2(v00, v01);
                *(float2*)&dst[(long)(gia + 8) * C_ + gj] = make_float2(v10, v11);
                if (bx != by) {
                    dst[(long)gj * C_ + gia]           = v00;
                    dst[(long)(gj + 1) * C_ + gia]     = v01;
                    dst[(long)gj * C_ + gia + 8]       = v10;
                    dst[(long)(gj + 1) * C_ + gia + 8] = v11;
                }
            } else if (mode == MODE_APPLY) {
                float sm0 = g_mean[1][bz][gia], sm1 = g_mean[1][bz][gia + 8];
                float* o0 = outp + ((long)bz * C_ + gia) * N_ + gj;
                *(float2*)o0 = make_float2(v00 + sm0, v01 + sm0);
                float* o1 = outp + ((long)bz * C_ + gia + 8) * N_ + gj;
                *(float2*)o1 = make_float2(v10 + sm1, v11 + sm1);
            } else {
                __nv_bfloat16 *dh, *dm;
                if (mode == MODE_G) {
                    dh = g_Gh[bz]; dm = g_Gm[bz];
                    v00 = -0.5f * v00 + ((gj     == gia)     ? 1.5f : 0.f);
                    v01 = -0.5f * v01 + ((gj + 1 == gia)     ? 1.5f : 0.f);
                    v10 = -0.5f * v10 + ((gj     == gia + 8) ? 1.5f : 0.f);
                    v11 = -0.5f * v11 + ((gj + 1 == gia + 8) ? 1.5f : 0.f);
                } else if (mode == MODE_YZ) {
                    int m = bz & 7;
                    if (bz < 8) { dh = g_Yh[flag ^ 1][m]; dm = g_Ym[flag ^ 1][m]; }
                    else        { dh = g_Zh[flag ^ 1][m]; dm = g_Zm[flag ^ 1][m]; }
                } else {
                    dh = g_Mh[bz]; dm = g_Mm[bz];
                    v00 *= alpha; v01 *= alpha; v10 *= alpha; v11 *= alpha;
                }
                __nv_bfloat16 h00, m00, h01, m01, h10, m10, h11, m11;
                split2(v00, h00, m00); split2(v01, h01, m01);
                split2(v10, h10, m10); split2(v11, h11, m11);
                __nv_bfloat162 ph0; ph0.x = h00; ph0.y = h01;
                __nv_bfloat162 pm0; pm0.x = m00; pm0.y = m01;
                __nv_bfloat162 ph1; ph1.x = h10; ph1.y = h11;
                __nv_bfloat162 pm1; pm1.x = m10; pm1.y = m11;
                *(__nv_bfloat162*)&dh[(long)gia * C_ + gj]       = ph0;
                *(__nv_bfloat162*)&dm[(long)gia * C_ + gj]       = pm0;
                *(__nv_bfloat162*)&dh[(long)(gia + 8) * C_ + gj] = ph1;
                *(__nv_bfloat162*)&dm[(long)(gia + 8) * C_ + gj] = pm1;
                if (sym && bx != by) {
                    dh[(long)gj * C_ + gia] = h00;           dm[(long)gj * C_ + gia] = m00;
                    dh[(long)(gj + 1) * C_ + gia] = h01;     dm[(long)(gj + 1) * C_ + gia] = m01;
                    dh[(long)gj * C_ + gia + 8] = h10;       dm[(long)gj * C_ + gia + 8] = m10;
                    dh[(long)(gj + 1) * C_ + gia + 8] = h11; dm[(long)(gj + 1) * C_ + gia + 8] = m11;
                }
            }
        }
    }
}

// ---------------- launch sequence (graph-capturable, deterministic) ----------------
extern "C" void kernel_launch(void* const* d_in, const int* in_sizes, int n_in,
                              void* d_out, int out_size)
{
    const float* content = (const float*)d_in[0];
    const float* style   = (const float*)d_in[1];
    float* out = (float*)d_out;

    cudaFuncSetAttribute(mma_kernel, cudaFuncAttributeMaxDynamicSharedMemorySize, SMEM_DYN);

    means_split_kernel<<<4096, 256>>>(content, style);

    mma_kernel<<<dim3(4, 4, NMAT * KSPLIT), 256, SMEM_DYN>>>(MODE_COV, 0, nullptr);
    cov_reduce_kernel<<<NMAT * C_ * C_ / 256, 256>>>();
    scale_finalize_kernel<<<1, 256>>>();
    init_ns_kernel<<<NMAT * C_ * C_ / 256, 256>>>();

    for (int it = 0; it < NS_ITERS; it++) {
        mma_kernel<<<dim3(4, 4, NMAT), 256, SMEM_DYN>>>(MODE_G, it & 1, nullptr);
        mma_kernel<<<dim3(4, 4, NMAT * 2), 256, SMEM_DYN>>>(MODE_YZ, it & 1, nullptr);
    }

    // NS_ITERS even -> final Y/Z live in buffer [0]
    mma_kernel<<<dim3(4, 4, B_), 256, SMEM_DYN>>>(MODE_COMBINE, 0, nullptr);
    mma_kernel<<<dim3(N_ / 128, 4, B_), 256, SMEM_DYN>>>(MODE_APPLY, 0, out);
}

// round 15
// speedup vs baseline: 1.6574x; 1.0697x over previous
#include <cuda_runtime.h>
#include <cuda_bf16.h>
#include <math.h>
#include <stdint.h>

#define C_    512
#define N_    16384
#define B_    4
#define NMAT  8
#define EPS_  1e-5f
#define NS_ITERS 4                // it0 shortcut (Z0=I), it3 halved; 4 effective iterations
#define SCALE_DIV 16.0f
#define KSPLIT 8
#define KSEG  (N_ / KSPLIT)       // 2048

#define MODE_COV     0
#define MODE_G       1
#define MODE_YZ      2
#define MODE_COMBINE 3
#define MODE_APPLY   4
#define MODE_YZF     5            // final-iter half update: Y for style, Z for content

// SMEM: A tensors 128 x 40(pad) bf16 = 10240B each.
// Normal-B modes: B tensors also 128 x 40 = 10240B each  -> stage 40960B
// Trans-B (APPLY): B tensors 32 rows x 136(pad) bf16 = 8704B each -> stage 37888B
#define TEN_BYTES   10240
#define BT_TEN      8704
#define STAGE_BYTES 40960
#define SMEM_DYN    81920

// ---------------- device scratch (no allocations allowed) ----------------
__device__ float g_mean[2][B_][C_];                  // [0]=content, [1]=style
__device__ float g_cov[NMAT][C_ * C_];
__device__ float g_covp[KSPLIT][NMAT][C_ * C_];      // split-K raw partials
__device__ float g_ssp[NMAT * 1024];                 // per-block Frobenius partials
__device__ float g_s[NMAT], g_sinv[NMAT];
__device__ __nv_bfloat16 g_xh[2][B_][C_][N_];        // centered hi  [src][b][c][n]
__device__ __nv_bfloat16 g_xm[2][B_][C_][N_];        // centered mid
__device__ __nv_bfloat16 g_Yh[2][NMAT][C_ * C_], g_Ym[2][NMAT][C_ * C_];
__device__ __nv_bfloat16 g_Zh[2][NMAT][C_ * C_], g_Zm[2][NMAT][C_ * C_];
__device__ __nv_bfloat16 g_Gh[NMAT][C_ * C_], g_Gm[NMAT][C_ * C_];
__device__ __nv_bfloat16 g_Mh[B_][C_ * C_], g_Mm[B_][C_ * C_];

// ---------------- PTX helpers (all sm_80+ features only) ----------------
__device__ __forceinline__ uint32_t smem_u32(const void* p) {
    uint32_t a;
    asm("{ .reg .u64 t; cvta.to.shared.u64 t, %1; cvt.u32.u64 %0, t; }" : "=r"(a) : "l"(p));
    return a;
}
#define CP_ASYNC(dst, src) asm volatile("cp.async.cg.shared.global [%0], [%1], 16;" :: "r"(dst), "l"(src))
#define CP_COMMIT()        asm volatile("cp.async.commit_group;" ::: "memory")
#define CP_WAIT1()         asm volatile("cp.async.wait_group 1;" ::: "memory")
#define CP_WAIT0()         asm volatile("cp.async.wait_group 0;" ::: "memory")

__device__ __forceinline__ void ldsm4(uint32_t* r, uint32_t addr) {
    asm volatile("ldmatrix.sync.aligned.m8n8.x4.shared.b16 {%0,%1,%2,%3}, [%4];"
        : "=r"(r[0]), "=r"(r[1]), "=r"(r[2]), "=r"(r[3]) : "r"(addr));
}
__device__ __forceinline__ void ldsm4t(uint32_t* r, uint32_t addr) {
    asm volatile("ldmatrix.sync.aligned.m8n8.x4.trans.shared.b16 {%0,%1,%2,%3}, [%4];"
        : "=r"(r[0]), "=r"(r[1]), "=r"(r[2]), "=r"(r[3]) : "r"(addr));
}
__device__ __forceinline__ void mma16816(float* c, const uint32_t* a, const uint32_t* b) {
    asm volatile("mma.sync.aligned.m16n8k16.row.col.f32.bf16.bf16.f32 "
        "{%0,%1,%2,%3}, {%4,%5,%6,%7}, {%8,%9}, {%0,%1,%2,%3};"
        : "+f"(c[0]), "+f"(c[1]), "+f"(c[2]), "+f"(c[3])
        : "r"(a[0]), "r"(a[1]), "r"(a[2]), "r"(a[3]), "r"(b[0]), "r"(b[1]));
}
__device__ __forceinline__ void split2(float v, __nv_bfloat16& h, __nv_bfloat16& m) {
    h = __float2bfloat16(v);
    m = __float2bfloat16(v - __bfloat162float(h));
}

// ---------------- fused means + center + split (single read of inputs) ----------------
__global__ __launch_bounds__(256) void means_split_kernel(
    const float* __restrict__ content, const float* __restrict__ style)
{
    int idx = blockIdx.x;
    int src = idx >> 11, b = (idx >> 9) & 3, c = idx & 511;
    const float4* X4 = (const float4*)((src ? style : content) + (size_t)(b * C_ + c) * N_);

    float4 v[16];
    float sum = 0.f;
#pragma unroll
    for (int j = 0; j < 16; j++) {
        v[j] = X4[threadIdx.x + j * 256];
        sum += (v[j].x + v[j].y) + (v[j].z + v[j].w);
    }
    __shared__ float red[256];
    red[threadIdx.x] = sum;
    __syncthreads();
    for (int s = 128; s; s >>= 1) {
        if (threadIdx.x < s) red[threadIdx.x] += red[threadIdx.x + s];
        __syncthreads();
    }
    float mu = red[0] * (1.0f / N_);
    if (threadIdx.x == 0) g_mean[src][b][c] = mu;

    __nv_bfloat162* H = (__nv_bfloat162*)&g_xh[src][b][c][0];
    __nv_bfloat162* M = (__nv_bfloat162*)&g_xm[src][b][c][0];
#pragma unroll
    for (int j = 0; j < 16; j++) {
        int i = threadIdx.x + j * 256;
        __nv_bfloat16 h0, m0, h1, m1, h2, m2, h3, m3;
        split2(v[j].x - mu, h0, m0); split2(v[j].y - mu, h1, m1);
        split2(v[j].z - mu, h2, m2); split2(v[j].w - mu, h3, m3);
        __nv_bfloat162 a, b2;
        a.x = h0; a.y = h1; b2.x = h2; b2.y = h3;
        H[2 * i] = a; H[2 * i + 1] = b2;
        a.x = m0; a.y = m1; b2.x = m2; b2.y = m3;
        M[2 * i] = a; M[2 * i + 1] = b2;
    }
}

// fold split-K partials: cov = sum(partials)*inv + eps*I ; also per-block Frobenius partials
__global__ __launch_bounds__(256) void cov_reduce_kernel()
{
    int i = blockIdx.x * 256 + threadIdx.x;   // 8 * 262144
    int m = i >> 18;
    int r = i & (C_ * C_ - 1);
    float v = 0.f;
#pragma unroll
    for (int s = 0; s < KSPLIT; s++) v += g_covp[s][m][r];
    v *= 1.0f / (float)(N_ - 1);
    if ((r >> 9) == (r & 511)) v += EPS_;
    g_cov[m][r] = v;

    // deterministic per-block Frobenius partial (block spans one matrix only)
    __shared__ float red[256];
    red[threadIdx.x] = v * v;
    __syncthreads();
    for (int s = 128; s; s >>= 1) {
        if (threadIdx.x < s) red[threadIdx.x] += red[threadIdx.x + s];
        __syncthreads();
    }
    if (threadIdx.x == 0) g_ssp[blockIdx.x] = red[0];
}

// finalize spectral scale: warp w reduces matrix w's 1024 partials (deterministic order)
__global__ __launch_bounds__(256) void scale_finalize_kernel()
{
    int w = threadIdx.x >> 5, l = threadIdx.x & 31;
    float s = 0.f;
#pragma unroll
    for (int j = 0; j < 32; j++) s += g_ssp[w * 1024 + j * 32 + l];
#pragma unroll
    for (int o = 16; o; o >>= 1) s += __shfl_xor_sync(0xFFFFFFFF, s, o);
    if (l == 0) {
        float sc = sqrtf(s) * (1.0f / SCALE_DIV);
        g_s[w] = sc;
        g_sinv[w] = 1.0f / sc;
    }
}

// Y0 = cov/s; iteration-0 shortcut: G1 = (3I - Y0)/2 elementwise, Z1 = G1.
// (Z0 = I never materialized; it0 then only needs Y1 = Y0*G1.)
__global__ __launch_bounds__(256) void init_ns_kernel()
{
    int i = blockIdx.x * 256 + threadIdx.x;   // 8 * 262144
    int m = i >> 18;
    int r = i & (C_ * C_ - 1);
    float v = g_cov[m][r] * g_sinv[m];
    __nv_bfloat16 h, mm;
    split2(v, h, mm);
    g_Yh[0][m][r] = h;
    g_Ym[0][m][r] = mm;
    bool dg = ((r >> 9) == (r & 511));
    float gv = (dg ? 1.5f : 0.0f) - 0.5f * v;
    __nv_bfloat16 gh, gm;
    split2(gv, gh, gm);
    g_Gh[m][r] = gh;  g_Gm[m][r] = gm;
    g_Zh[1][m][r] = gh; g_Zm[1][m][r] = gm;   // Z1 = G1
}

// ---------------- cp.async stage fill ----------------
// normal: A,B both [row][k] 128 x 32, stride-40 pad
__device__ __forceinline__ void fill_stage(uint32_t sbase,
    const __nv_bfloat16* ah, const __nv_bfloat16* am,
    const __nv_bfloat16* bh, const __nv_bfloat16* bm,
    long sA, long sB, int tid)
{
#pragma unroll
    for (int t = tid; t < 512; t += 256) {
        int row = t >> 2, q = (t & 3) * 8;
        uint32_t d = sbase + (uint32_t)(row * 40 + q) * 2;
        long oa = (long)row * sA + q, ob = (long)row * sB + q;
        CP_ASYNC(d,                 ah + oa);
        CP_ASYNC(d + TEN_BYTES,     am + oa);
        CP_ASYNC(d + 2 * TEN_BYTES, bh + ob);
        CP_ASYNC(d + 3 * TEN_BYTES, bm + ob);
    }
}

// trans-B (APPLY): A [i][k] 128 x 32 stride-40; B natural [k][n] 32 x 128, stride-136 pad
__device__ __forceinline__ void fill_stage_t(uint32_t sbase,
    const __nv_bfloat16* ah, const __nv_bfloat16* am,
    const __nv_bfloat16* bh, const __nv_bfloat16* bm, int tid)
{
#pragma unroll
    for (int t = tid; t < 512; t += 256) {
        int row = t >> 2, q = (t & 3) * 8;
        uint32_t d = sbase + (uint32_t)(row * 40 + q) * 2;
        long oa = (long)row * C_ + q;
        CP_ASYNC(d,             ah + oa);
        CP_ASYNC(d + TEN_BYTES, am + oa);
    }
#pragma unroll
    for (int t = tid; t < 512; t += 256) {
        int row = t >> 4, q = (t & 15) * 8;
        uint32_t d = sbase + 2 * TEN_BYTES + (uint32_t)(row * 136 + q) * 2;
        long ob = (long)row * N_ + q;
        CP_ASYNC(d,          bh + ob);
        CP_ASYNC(d + BT_TEN, bm + ob);
    }
}

// ---------------- 128-tile warp-MMA kernel: D(128x128) = A * B^T, bf16 hi/mid 3-pass ----------------
__global__ __launch_bounds__(256, 2) void mma_kernel(int mode, int flag, float* __restrict__ outp)
{
    int bx = blockIdx.x, by = blockIdx.y, bz = blockIdx.z;
    bool sym = (mode <= MODE_YZ || mode == MODE_YZF);
    if (sym && by > bx) return;               // upper-triangle tiles only; mirror in epilogue
    int i0 = by * 128, j0 = bx * 128;
    bool btrans = (mode == MODE_APPLY);

    const __nv_bfloat16 *Ah, *Am, *Bh, *Bm;
    long sA, sB;
    int K;
    int mz = bz, sK = 0;
    if (mode == MODE_COV) {
        mz = bz & 7; sK = bz >> 3;            // mat, K-split
        int src = mz >> 2, b = mz & 3;
        long ks = (long)sK * KSEG;
        Ah = &g_xh[src][b][i0][0] + ks; Am = &g_xm[src][b][i0][0] + ks;
        Bh = &g_xh[src][b][j0][0] + ks; Bm = &g_xm[src][b][j0][0] + ks;
        sA = sB = N_; K = KSEG;
    } else if (mode == MODE_G) {              // G = (3I - Z*Y)/2 ; D = Z * Y^T (Y sym)
        Ah = g_Zh[flag][bz] + (long)i0 * C_; Am = g_Zm[flag][bz] + (long)i0 * C_;
        Bh = g_Yh[flag][bz] + (long)j0 * C_; Bm = g_Ym[flag][bz] + (long)j0 * C_;
        sA = sB = C_; K = C_;
    } else if (mode == MODE_YZ) {
        int m = bz & 7;
        sA = sB = C_; K = C_;
        if (bz < 8) {                          // Ynew = Y * G   (G sym)
            Ah = g_Yh[flag][m] + (long)i0 * C_; Am = g_Ym[flag][m] + (long)i0 * C_;
            Bh = g_Gh[m] + (long)j0 * C_;       Bm = g_Gm[m] + (long)j0 * C_;
        } else {                               // Znew = G * Z   (Z sym)
            Ah = g_Gh[m] + (long)i0 * C_;       Am = g_Gm[m] + (long)i0 * C_;
            Bh = g_Zh[flag][m] + (long)j0 * C_; Bm = g_Zm[flag][m] + (long)j0 * C_;
        }
    } else if (mode == MODE_YZF) {             // final iter: Y for style mats, Z for content mats
        sA = sB = C_; K = C_;
        if (bz < 4) {
            int m = 4 + bz;                    // Ynew (style)
            Ah = g_Yh[flag][m] + (long)i0 * C_; Am = g_Ym[flag][m] + (long)i0 * C_;
            Bh = g_Gh[m] + (long)j0 * C_;       Bm = g_Gm[m] + (long)j0 * C_;
        } else {
            int m = bz - 4;                    // Znew (content)
            Ah = g_Gh[m] + (long)i0 * C_;       Am = g_Gm[m] + (long)i0 * C_;
            Bh = g_Zh[flag][m] + (long)j0 * C_; Bm = g_Zm[flag][m] + (long)j0 * C_;
        }
    } else if (mode == MODE_COMBINE) {         // M = alpha * Y_style * Z_content^T
        Ah = g_Yh[0][4 + bz] + (long)i0 * C_; Am = g_Ym[0][4 + bz] + (long)i0 * C_;
        Bh = g_Zh[0][bz] + (long)j0 * C_;     Bm = g_Zm[0][bz] + (long)j0 * C_;
        sA = sB = C_; K = C_;
    } else {                                   // APPLY: out = M * Xc (+ s_mean); B natural [k][n]
        Ah = g_Mh[bz] + (long)i0 * C_;       Am = g_Mm[bz] + (long)i0 * C_;
        Bh = &g_xh[0][bz][0][j0];            Bm = &g_xm[0][bz][0][j0];
        sA = C_; sB = N_; K = C_;
    }

    extern __shared__ char dsm[];
    uint32_t sb = smem_u32(dsm);
    int tid = threadIdx.x, wid = tid >> 5, l = tid & 31;
    int wr = wid & 3, wc = wid >> 2;            // warp grid 4 (m) x 2 (n)

    // lane-invariant ldmatrix offsets (bytes, kk=0)
    uint32_t aoff[2], boff[4];
#pragma unroll
    for (int t = 0; t < 2; t++)
        aoff[t] = (uint32_t)(((wr * 32 + t * 16 + (l & 15)) * 40 + ((l >> 4) << 3)) * 2);
    int g = l >> 3;
    if (!btrans) {
#pragma unroll
        for (int jp = 0; jp < 4; jp++) {
            int row = wc * 64 + jp * 16 + (l & 7) + ((g >= 2) ? 8 : 0);
            boff[jp] = (uint32_t)((row * 40 + ((g & 1) << 3)) * 2);
        }
    } else {
        // trans ldsm from [k][n]: g0:(k0-7,n0-7) g1:(k8-15,n0-7) g2:(k0-7,n8-15) g3:(k8-15,n8-15)
        int krow = (l & 7) + ((g & 1) ? 8 : 0);
#pragma unroll
        for (int jp = 0; jp < 4; jp++) {
            int ncol = wc * 64 + jp * 16 + ((g >= 2) ? 8 : 0);
            boff[jp] = (uint32_t)((krow * 136 + ncol) * 2);
        }
    }
    uint32_t bkof = btrans ? (uint32_t)(16 * 136 * 2) : 32u;  // kk -> +16 k

    float acc[2][8][4];
#pragma unroll
    for (int t = 0; t < 2; t++)
#pragma unroll
        for (int j = 0; j < 8; j++)
#pragma unroll
            for (int q = 0; q < 4; q++) acc[t][j][q] = 0.f;

    int nch = K / 32;
    if (!btrans) {
        fill_stage(sb, Ah, Am, Bh, Bm, sA, sB, tid); CP_COMMIT();
        fill_stage(sb + STAGE_BYTES, Ah + 32, Am + 32, Bh + 32, Bm + 32, sA, sB, tid); CP_COMMIT();
    } else {
        fill_stage_t(sb, Ah, Am, Bh, Bm, tid); CP_COMMIT();
        fill_stage_t(sb + STAGE_BYTES, Ah + 32, Am + 32, Bh + 32 * N_, Bm + 32 * N_, tid); CP_COMMIT();
    }

    for (int c = 0; c < nch; c++) {
        if (c + 1 < nch) CP_WAIT1(); else CP_WAIT0();
        __syncthreads();
        uint32_t stb = sb + (uint32_t)(c & 1) * STAGE_BYTES;
#pragma unroll
        for (int kk = 0; kk < 2; kk++) {
            uint32_t kofA = (uint32_t)kk * 32;
            uint32_t kofB = (uint32_t)kk * bkof;
            uint32_t fa[2][4], fm[2][4];
            ldsm4(fa[0], stb + aoff[0] + kofA);
            ldsm4(fa[1], stb + aoff[1] + kofA);
            ldsm4(fm[0], stb + TEN_BYTES + aoff[0] + kofA);
            ldsm4(fm[1], stb + TEN_BYTES + aoff[1] + kofA);
#pragma unroll
            for (int jp = 0; jp < 4; jp++) {
                uint32_t bh[4], bm2[4];
                if (!btrans) {
                    ldsm4(bh,  stb + 2 * TEN_BYTES + boff[jp] + kofB);
                    ldsm4(bm2, stb + 3 * TEN_BYTES + boff[jp] + kofB);
                } else {
                    ldsm4t(bh,  stb + 2 * TEN_BYTES + boff[jp] + kofB);
                    ldsm4t(bm2, stb + 2 * TEN_BYTES + BT_TEN + boff[jp] + kofB);
                }
                // pass-outer ordering: 4 independent accumulators between RAW reuses
                mma16816(acc[0][2 * jp],     fa[0], &bh[0]);
                mma16816(acc[0][2 * jp + 1], fa[0], &bh[2]);
                mma16816(acc[1][2 * jp],     fa[1], &bh[0]);
                mma16816(acc[1][2 * jp + 1], fa[1], &bh[2]);
                mma16816(acc[0][2 * jp],     fa[0], &bm2[0]);
                mma16816(acc[0][2 * jp + 1], fa[0], &bm2[2]);
                mma16816(acc[1][2 * jp],     fa[1], &bm2[0]);
                mma16816(acc[1][2 * jp + 1], fa[1], &bm2[2]);
                mma16816(acc[0][2 * jp],     fm[0], &bh[0]);
                mma16816(acc[0][2 * jp + 1], fm[0], &bh[2]);
                mma16816(acc[1][2 * jp],     fm[1], &bh[0]);
                mma16816(acc[1][2 * jp + 1], fm[1], &bh[2]);
            }
        }
        __syncthreads();
        if (c + 2 < nch) {
            long ko = (long)(c + 2) * 32;
            uint32_t dstb = sb + (uint32_t)(c & 1) * STAGE_BYTES;
            if (!btrans)
                fill_stage(dstb, Ah + ko, Am + ko, Bh + ko, Bm + ko, sA, sB, tid);
            else
                fill_stage_t(dstb, Ah + ko, Am + ko, Bh + ko * N_, Bm + ko * N_, tid);
            CP_COMMIT();
        }
    }

    // ---------------- epilogue straight from registers ----------------
    int r0 = l >> 2, cp2 = (l & 3) * 2;
    float alpha = (mode == MODE_COMBINE) ? sqrtf(g_s[4 + bz] / g_s[bz]) : 1.0f;

#pragma unroll
    for (int t = 0; t < 2; t++) {
        int gia = i0 + wr * 32 + t * 16 + r0;     // rows gia, gia+8
#pragma unroll
        for (int j = 0; j < 8; j++) {
            int gj = j0 + wc * 64 + j * 8 + cp2;  // cols gj, gj+1
            float v00 = acc[t][j][0], v01 = acc[t][j][1];
            float v10 = acc[t][j][2], v11 = acc[t][j][3];

            if (mode == MODE_COV) {
                float* dst = &g_covp[sK][mz][0];   // raw partial sums
                *(float2*)&dst[(long)gia * C_ + gj]       = make_float2(v00, v01);
                *(float2*)&dst[(long)(gia + 8) * C_ + gj] = make_float2(v10, v11);
                if (bx != by) {
                    dst[(long)gj * C_ + gia]           = v00;
                    dst[(long)(gj + 1) * C_ + gia]     = v01;
                    dst[(long)gj * C_ + gia + 8]       = v10;
                    dst[(long)(gj + 1) * C_ + gia + 8] = v11;
                }
            } else if (mode == MODE_APPLY) {
                float sm0 = g_mean[1][bz][gia], sm1 = g_mean[1][bz][gia + 8];
                float* o0 = outp + ((long)bz * C_ + gia) * N_ + gj;
                *(float2*)o0 = make_float2(v00 + sm0, v01 + sm0);
                float* o1 = outp + ((long)bz * C_ + gia + 8) * N_ + gj;
                *(float2*)o1 = make_float2(v10 + sm1, v11 + sm1);
            } else {
                __nv_bfloat16 *dh, *dm;
                if (mode == MODE_G) {
                    dh = g_Gh[bz]; dm = g_Gm[bz];
                    v00 = -0.5f * v00 + ((gj     == gia)     ? 1.5f : 0.f);
                    v01 = -0.5f * v01 + ((gj + 1 == gia)     ? 1.5f : 0.f);
                    v10 = -0.5f * v10 + ((gj     == gia + 8) ? 1.5f : 0.f);
                    v11 = -0.5f * v11 + ((gj + 1 == gia + 8) ? 1.5f : 0.f);
                } else if (mode == MODE_YZ) {
                    int m = bz & 7;
                    if (bz < 8) { dh = g_Yh[flag ^ 1][m]; dm = g_Ym[flag ^ 1][m]; }
                    else        { dh = g_Zh[flag ^ 1][m]; dm = g_Zm[flag ^ 1][m]; }
                } else if (mode == MODE_YZF) {
                    if (bz < 4) { dh = g_Yh[flag ^ 1][4 + bz]; dm = g_Ym[flag ^ 1][4 + bz]; }
                    else        { dh = g_Zh[flag ^ 1][bz - 4]; dm = g_Zm[flag ^ 1][bz - 4]; }
                } else {
                    dh = g_Mh[bz]; dm = g_Mm[bz];
                    v00 *= alpha; v01 *= alpha; v10 *= alpha; v11 *= alpha;
                }
                __nv_bfloat16 h00, m00, h01, m01, h10, m10, h11, m11;
                split2(v00, h00, m00); split2(v01, h01, m01);
                split2(v10, h10, m10); split2(v11, h11, m11);
                __nv_bfloat162 ph0; ph0.x = h00; ph0.y = h01;
                __nv_bfloat162 pm0; pm0.x = m00; pm0.y = m01;
                __nv_bfloat162 ph1; ph1.x = h10; ph1.y = h11;
                __nv_bfloat162 pm1; pm1.x = m10; pm1.y = m11;
                *(__nv_bfloat162*)&dh[(long)gia * C_ + gj]       = ph0;
                *(__nv_bfloat162*)&dm[(long)gia * C_ + gj]       = pm0;
                *(__nv_bfloat162*)&dh[(long)(gia + 8) * C_ + gj] = ph1;
                *(__nv_bfloat162*)&dm[(long)(gia + 8) * C_ + gj] = pm1;
                if (sym && bx != by) {
                    dh[(long)gj * C_ + gia] = h00;           dm[(long)gj * C_ + gia] = m00;
                    dh[(long)(gj + 1) * C_ + gia] = h01;     dm[(long)(gj + 1) * C_ + gia] = m01;
                    dh[(long)gj * C_ + gia + 8] = h10;       dm[(long)gj * C_ + gia + 8] = m10;
                    dh[(long)(gj + 1) * C_ + gia + 8] = h11; dm[(long)(gj + 1) * C_ + gia + 8] = m11;
                }
            }
        }
    }
}

// ---------------- launch sequence (graph-capturable, deterministic) ----------------
extern "C" void kernel_launch(void* const* d_in, const int* in_sizes, int n_in,
                              void* d_out, int out_size)
{
    const float* content = (const float*)d_in[0];
    const float* style   = (const float*)d_in[1];
    float* out = (float*)d_out;

    cudaFuncSetAttribute(mma_kernel, cudaFuncAttributeMaxDynamicSharedMemorySize, SMEM_DYN);

    means_split_kernel<<<4096, 256>>>(content, style);

    mma_kernel<<<dim3(4, 4, NMAT * KSPLIT), 256, SMEM_DYN>>>(MODE_COV, 0, nullptr);
    cov_reduce_kernel<<<NMAT * C_ * C_ / 256, 256>>>();
    scale_finalize_kernel<<<1, 256>>>();
    init_ns_kernel<<<NMAT * C_ * C_ / 256, 256>>>();   // writes Y0, G1, Z1=G1

    // it0 (flag 0): G1/Z1 already done by init; only Y1 = Y0*G1 (8 Y-jobs)
    mma_kernel<<<dim3(4, 4, NMAT), 256, SMEM_DYN>>>(MODE_YZ, 0, nullptr);
    // it1 (flag 1), it2 (flag 0): full iterations
    for (int it = 1; it < NS_ITERS - 1; it++) {
        mma_kernel<<<dim3(4, 4, NMAT), 256, SMEM_DYN>>>(MODE_G, it & 1, nullptr);
        mma_kernel<<<dim3(4, 4, NMAT * 2), 256, SMEM_DYN>>>(MODE_YZ, it & 1, nullptr);
    }
    // it3 (flag 1): G full, then only Y_style + Z_content (8 jobs); writes buffer [0]
    mma_kernel<<<dim3(4, 4, NMAT), 256, SMEM_DYN>>>(MODE_G, 1, nullptr);
    mma_kernel<<<dim3(4, 4, NMAT), 256, SMEM_DYN>>>(MODE_YZF, 1, nullptr);

    mma_kernel<<<dim3(4, 4, B_), 256, SMEM_DYN>>>(MODE_COMBINE, 0, nullptr);
    mma_kernel<<<dim3(N_ / 128, 4, B_), 256, SMEM_DYN>>>(MODE_APPLY, 0, out);
}

// round 16
// speedup vs baseline: 1.6589x; 1.0009x over previous
#include <cuda_runtime.h>
#include <cuda_bf16.h>
#include <math.h>
#include <stdint.h>

#define C_    512
#define N_    16384
#define B_    4
#define NMAT  8
#define EPS_  1e-5f
#define NS_ITERS 4                // it0 shortcut (Z0=I), it3 halved; 4 effective iterations
#define SCALE_DIV 16.0f
#define KSPLIT 16
#define KSEG  (N_ / KSPLIT)       // 1024

#define MODE_COV     0
#define MODE_G       1
#define MODE_YZ      2
#define MODE_COMBINE 3
#define MODE_APPLY   4
#define MODE_YZF     5            // final-iter half update: Y for style, Z for content

// SMEM: A tensors 128 x 40(pad) bf16 = 10240B each.
// Normal-B modes: B tensors also 128 x 40 = 10240B each  -> stage 40960B
// Trans-B (APPLY): B tensors 32 rows x 136(pad) bf16 = 8704B each -> stage 37888B
#define TEN_BYTES   10240
#define BT_TEN      8704
#define STAGE_BYTES 40960
#define SMEM_DYN    81920

// ---------------- device scratch (no allocations allowed) ----------------
__device__ float g_mean[2][B_][C_];                  // [0]=content, [1]=style
__device__ float g_cov[NMAT][C_ * C_];
__device__ float g_covp[KSPLIT][NMAT][C_ * C_];      // split-K raw partials (upper tiles only)
__device__ float g_ssp[NMAT * 1024];                 // per-block Frobenius partials
__device__ float g_s[NMAT], g_sinv[NMAT];
__device__ __nv_bfloat16 g_xh[2][B_][C_][N_];        // centered hi  [src][b][c][n]
__device__ __nv_bfloat16 g_xm[2][B_][C_][N_];        // centered mid
__device__ __nv_bfloat16 g_Yh[2][NMAT][C_ * C_], g_Ym[2][NMAT][C_ * C_];
__device__ __nv_bfloat16 g_Zh[2][NMAT][C_ * C_], g_Zm[2][NMAT][C_ * C_];
__device__ __nv_bfloat16 g_Gh[NMAT][C_ * C_], g_Gm[NMAT][C_ * C_];
__device__ __nv_bfloat16 g_Mh[B_][C_ * C_], g_Mm[B_][C_ * C_];

// ---------------- PTX helpers (all sm_80+ features only) ----------------
__device__ __forceinline__ uint32_t smem_u32(const void* p) {
    uint32_t a;
    asm("{ .reg .u64 t; cvta.to.shared.u64 t, %1; cvt.u32.u64 %0, t; }" : "=r"(a) : "l"(p));
    return a;
}
#define CP_ASYNC(dst, src) asm volatile("cp.async.cg.shared.global [%0], [%1], 16;" :: "r"(dst), "l"(src))
#define CP_COMMIT()        asm volatile("cp.async.commit_group;" ::: "memory")
#define CP_WAIT1()         asm volatile("cp.async.wait_group 1;" ::: "memory")
#define CP_WAIT0()         asm volatile("cp.async.wait_group 0;" ::: "memory")

__device__ __forceinline__ void ldsm4(uint32_t* r, uint32_t addr) {
    asm volatile("ldmatrix.sync.aligned.m8n8.x4.shared.b16 {%0,%1,%2,%3}, [%4];"
        : "=r"(r[0]), "=r"(r[1]), "=r"(r[2]), "=r"(r[3]) : "r"(addr));
}
__device__ __forceinline__ void ldsm4t(uint32_t* r, uint32_t addr) {
    asm volatile("ldmatrix.sync.aligned.m8n8.x4.trans.shared.b16 {%0,%1,%2,%3}, [%4];"
        : "=r"(r[0]), "=r"(r[1]), "=r"(r[2]), "=r"(r[3]) : "r"(addr));
}
__device__ __forceinline__ void mma16816(float* c, const uint32_t* a, const uint32_t* b) {
    asm volatile("mma.sync.aligned.m16n8k16.row.col.f32.bf16.bf16.f32 "
        "{%0,%1,%2,%3}, {%4,%5,%6,%7}, {%8,%9}, {%0,%1,%2,%3};"
        : "+f"(c[0]), "+f"(c[1]), "+f"(c[2]), "+f"(c[3])
        : "r"(a[0]), "r"(a[1]), "r"(a[2]), "r"(a[3]), "r"(b[0]), "r"(b[1]));
}
__device__ __forceinline__ void split2(float v, __nv_bfloat16& h, __nv_bfloat16& m) {
    h = __float2bfloat16(v);
    m = __float2bfloat16(v - __bfloat162float(h));
}

// ---------------- fused means + center + split (single read of inputs) ----------------
__global__ __launch_bounds__(256) void means_split_kernel(
    const float* __restrict__ content, const float* __restrict__ style)
{
    int idx = blockIdx.x;
    int src = idx >> 11, b = (idx >> 9) & 3, c = idx & 511;
    const float4* X4 = (const float4*)((src ? style : content) + (size_t)(b * C_ + c) * N_);

    float4 v[16];
    float sum = 0.f;
#pragma unroll
    for (int j = 0; j < 16; j++) {
        v[j] = X4[threadIdx.x + j * 256];
        sum += (v[j].x + v[j].y) + (v[j].z + v[j].w);
    }
    __shared__ float red[256];
    red[threadIdx.x] = sum;
    __syncthreads();
    for (int s = 128; s; s >>= 1) {
        if (threadIdx.x < s) red[threadIdx.x] += red[threadIdx.x + s];
        __syncthreads();
    }
    float mu = red[0] * (1.0f / N_);
    if (threadIdx.x == 0) g_mean[src][b][c] = mu;

    __nv_bfloat162* H = (__nv_bfloat162*)&g_xh[src][b][c][0];
    __nv_bfloat162* M = (__nv_bfloat162*)&g_xm[src][b][c][0];
#pragma unroll
    for (int j = 0; j < 16; j++) {
        int i = threadIdx.x + j * 256;
        __nv_bfloat16 h0, m0, h1, m1, h2, m2, h3, m3;
        split2(v[j].x - mu, h0, m0); split2(v[j].y - mu, h1, m1);
        split2(v[j].z - mu, h2, m2); split2(v[j].w - mu, h3, m3);
        __nv_bfloat162 a, b2;
        a.x = h0; a.y = h1; b2.x = h2; b2.y = h3;
        H[2 * i] = a; H[2 * i + 1] = b2;
        a.x = m0; a.y = m1; b2.x = m2; b2.y = m3;
        M[2 * i] = a; M[2 * i + 1] = b2;
    }
}

// fold split-K partials: cov = sum(partials)*inv + eps*I ; also per-block Frobenius partials.
// Partials hold only upper-triangle TILES (bx >= by); lower-tile elements read transposed.
__global__ __launch_bounds__(256) void cov_reduce_kernel()
{
    int i = blockIdx.x * 256 + threadIdx.x;   // 8 * 262144
    int m = i >> 18;
    int r = i & (C_ * C_ - 1);
    int ri = r >> 9, rj = r & 511;
    long src = ((ri >> 7) > (rj >> 7)) ? ((long)rj * C_ + ri) : (long)r;
    float v = 0.f;
#pragma unroll
    for (int s = 0; s < KSPLIT; s++) v += g_covp[s][m][src];
    v *= 1.0f / (float)(N_ - 1);
    if (ri == rj) v += EPS_;
    g_cov[m][r] = v;

    // deterministic per-block Frobenius partial (block spans one matrix only)
    __shared__ float red[256];
    red[threadIdx.x] = v * v;
    __syncthreads();
    for (int s = 128; s; s >>= 1) {
        if (threadIdx.x < s) red[threadIdx.x] += red[threadIdx.x + s];
        __syncthreads();
    }
    if (threadIdx.x == 0) g_ssp[blockIdx.x] = red[0];
}

// finalize spectral scale: warp w reduces matrix w's 1024 partials (deterministic order)
__global__ __launch_bounds__(256) void scale_finalize_kernel()
{
    int w = threadIdx.x >> 5, l = threadIdx.x & 31;
    float s = 0.f;
#pragma unroll
    for (int j = 0; j < 32; j++) s += g_ssp[w * 1024 + j * 32 + l];
#pragma unroll
    for (int o = 16; o; o >>= 1) s += __shfl_xor_sync(0xFFFFFFFF, s, o);
    if (l == 0) {
        float sc = sqrtf(s) * (1.0f / SCALE_DIV);
        g_s[w] = sc;
        g_sinv[w] = 1.0f / sc;
    }
}

// Y0 = cov/s; iteration-0 shortcut: G1 = (3I - Y0)/2 elementwise, Z1 = G1.
__global__ __launch_bounds__(256) void init_ns_kernel()
{
    int i = blockIdx.x * 256 + threadIdx.x;   // 8 * 262144
    int m = i >> 18;
    int r = i & (C_ * C_ - 1);
    float v = g_cov[m][r] * g_sinv[m];
    __nv_bfloat16 h, mm;
    split2(v, h, mm);
    g_Yh[0][m][r] = h;
    g_Ym[0][m][r] = mm;
    bool dg = ((r >> 9) == (r & 511));
    float gv = (dg ? 1.5f : 0.0f) - 0.5f * v;
    __nv_bfloat16 gh, gm;
    split2(gv, gh, gm);
    g_Gh[m][r] = gh;  g_Gm[m][r] = gm;
    g_Zh[1][m][r] = gh; g_Zm[1][m][r] = gm;   // Z1 = G1
}

// ---------------- cp.async stage fill ----------------
// normal: A,B both [row][k] 128 x 32, stride-40 pad
__device__ __forceinline__ void fill_stage(uint32_t sbase,
    const __nv_bfloat16* ah, const __nv_bfloat16* am,
    const __nv_bfloat16* bh, const __nv_bfloat16* bm,
    long sA, long sB, int tid)
{
#pragma unroll
    for (int t = tid; t < 512; t += 256) {
        int row = t >> 2, q = (t & 3) * 8;
        uint32_t d = sbase + (uint32_t)(row * 40 + q) * 2;
        long oa = (long)row * sA + q, ob = (long)row * sB + q;
        CP_ASYNC(d,                 ah + oa);
        CP_ASYNC(d + TEN_BYTES,     am + oa);
        CP_ASYNC(d + 2 * TEN_BYTES, bh + ob);
        CP_ASYNC(d + 3 * TEN_BYTES, bm + ob);
    }
}

// trans-B (APPLY): A [i][k] 128 x 32 stride-40; B natural [k][n] 32 x 128, stride-136 pad
__device__ __forceinline__ void fill_stage_t(uint32_t sbase,
    const __nv_bfloat16* ah, const __nv_bfloat16* am,
    const __nv_bfloat16* bh, const __nv_bfloat16* bm, int tid)
{
#pragma unroll
    for (int t = tid; t < 512; t += 256) {
        int row = t >> 2, q = (t & 3) * 8;
        uint32_t d = sbase + (uint32_t)(row * 40 + q) * 2;
        long oa = (long)row * C_ + q;
        CP_ASYNC(d,             ah + oa);
        CP_ASYNC(d + TEN_BYTES, am + oa);
    }
#pragma unroll
    for (int t = tid; t < 512; t += 256) {
        int row = t >> 4, q = (t & 15) * 8;
        uint32_t d = sbase + 2 * TEN_BYTES + (uint32_t)(row * 136 + q) * 2;
        long ob = (long)row * N_ + q;
        CP_ASYNC(d,          bh + ob);
        CP_ASYNC(d + BT_TEN, bm + ob);
    }
}

// ---------------- 128-tile warp-MMA kernel: D(128x128) = A * B^T, bf16 hi/mid 3-pass ----------------
__global__ __launch_bounds__(256, 2) void mma_kernel(int mode, int flag, float* __restrict__ outp)
{
    int bx = blockIdx.x, by = blockIdx.y, bz = blockIdx.z;
    bool sym = (mode <= MODE_YZ || mode == MODE_YZF);
    if (sym && by > bx) return;               // upper-triangle tiles only
    int i0 = by * 128, j0 = bx * 128;
    bool btrans = (mode == MODE_APPLY);

    const __nv_bfloat16 *Ah, *Am, *Bh, *Bm;
    long sA, sB;
    int K;
    int mz = bz, sK = 0;
    if (mode == MODE_COV) {
        mz = bz & 7; sK = bz >> 3;            // mat, K-split
        int src = mz >> 2, b = mz & 3;
        long ks = (long)sK * KSEG;
        Ah = &g_xh[src][b][i0][0] + ks; Am = &g_xm[src][b][i0][0] + ks;
        Bh = &g_xh[src][b][j0][0] + ks; Bm = &g_xm[src][b][j0][0] + ks;
        sA = sB = N_; K = KSEG;
    } else if (mode == MODE_G) {              // G = (3I - Z*Y)/2 ; D = Z * Y^T (Y sym)
        Ah = g_Zh[flag][bz] + (long)i0 * C_; Am = g_Zm[flag][bz] + (long)i0 * C_;
        Bh = g_Yh[flag][bz] + (long)j0 * C_; Bm = g_Ym[flag][bz] + (long)j0 * C_;
        sA = sB = C_; K = C_;
    } else if (mode == MODE_YZ) {
        int m = bz & 7;
        sA = sB = C_; K = C_;
        if (bz < 8) {                          // Ynew = Y * G   (G sym)
            Ah = g_Yh[flag][m] + (long)i0 * C_; Am = g_Ym[flag][m] + (long)i0 * C_;
            Bh = g_Gh[m] + (long)j0 * C_;       Bm = g_Gm[m] + (long)j0 * C_;
        } else {                               // Znew = G * Z   (Z sym)
            Ah = g_Gh[m] + (long)i0 * C_;       Am = g_Gm[m] + (long)i0 * C_;
            Bh = g_Zh[flag][m] + (long)j0 * C_; Bm = g_Zm[flag][m] + (long)j0 * C_;
        }
    } else if (mode == MODE_YZF) {             // final iter: Y for style mats, Z for content mats
        sA = sB = C_; K = C_;
        if (bz < 4) {
            int m = 4 + bz;                    // Ynew (style)
            Ah = g_Yh[flag][m] + (long)i0 * C_; Am = g_Ym[flag][m] + (long)i0 * C_;
            Bh = g_Gh[m] + (long)j0 * C_;       Bm = g_Gm[m] + (long)j0 * C_;
        } else {
            int m = bz - 4;                    // Znew (content)
            Ah = g_Gh[m] + (long)i0 * C_;       Am = g_Gm[m] + (long)i0 * C_;
            Bh = g_Zh[flag][m] + (long)j0 * C_; Bm = g_Zm[flag][m] + (long)j0 * C_;
        }
    } else if (mode == MODE_COMBINE) {         // M = alpha * Y_style * Z_content^T
        Ah = g_Yh[0][4 + bz] + (long)i0 * C_; Am = g_Ym[0][4 + bz] + (long)i0 * C_;
        Bh = g_Zh[0][bz] + (long)j0 * C_;     Bm = g_Zm[0][bz] + (long)j0 * C_;
        sA = sB = C_; K = C_;
    } else {                                   // APPLY: out = M * Xc (+ s_mean); B natural [k][n]
        Ah = g_Mh[bz] + (long)i0 * C_;       Am = g_Mm[bz] + (long)i0 * C_;
        Bh = &g_xh[0][bz][0][j0];            Bm = &g_xm[0][bz][0][j0];
        sA = C_; sB = N_; K = C_;
    }

    extern __shared__ char dsm[];
    uint32_t sb = smem_u32(dsm);
    int tid = threadIdx.x, wid = tid >> 5, l = tid & 31;
    int wr = wid & 3, wc = wid >> 2;            // warp grid 4 (m) x 2 (n)

    // lane-invariant ldmatrix offsets (bytes, kk=0)
    uint32_t aoff[2], boff[4];
#pragma unroll
    for (int t = 0; t < 2; t++)
        aoff[t] = (uint32_t)(((wr * 32 + t * 16 + (l & 15)) * 40 + ((l >> 4) << 3)) * 2);
    int g = l >> 3;
    if (!btrans) {
#pragma unroll
        for (int jp = 0; jp < 4; jp++) {
            int row = wc * 64 + jp * 16 + (l & 7) + ((g >= 2) ? 8 : 0);
            boff[jp] = (uint32_t)((row * 40 + ((g & 1) << 3)) * 2);
        }
    } else {
        // trans ldsm from [k][n]: g0:(k0-7,n0-7) g1:(k8-15,n0-7) g2:(k0-7,n8-15) g3:(k8-15,n8-15)
        int krow = (l & 7) + ((g & 1) ? 8 : 0);
#pragma unroll
        for (int jp = 0; jp < 4; jp++) {
            int ncol = wc * 64 + jp * 16 + ((g >= 2) ? 8 : 0);
            boff[jp] = (uint32_t)((krow * 136 + ncol) * 2);
        }
    }
    uint32_t bkof = btrans ? (uint32_t)(16 * 136 * 2) : 32u;  // kk -> +16 k

    float acc[2][8][4];
#pragma unroll
    for (int t = 0; t < 2; t++)
#pragma unroll
        for (int j = 0; j < 8; j++)
#pragma unroll
            for (int q = 0; q < 4; q++) acc[t][j][q] = 0.f;

    int nch = K / 32;
    if (!btrans) {
        fill_stage(sb, Ah, Am, Bh, Bm, sA, sB, tid); CP_COMMIT();
        fill_stage(sb + STAGE_BYTES, Ah + 32, Am + 32, Bh + 32, Bm + 32, sA, sB, tid); CP_COMMIT();
    } else {
        fill_stage_t(sb, Ah, Am, Bh, Bm, tid); CP_COMMIT();
        fill_stage_t(sb + STAGE_BYTES, Ah + 32, Am + 32, Bh + 32 * N_, Bm + 32 * N_, tid); CP_COMMIT();
    }

    for (int c = 0; c < nch; c++) {
        if (c + 1 < nch) CP_WAIT1(); else CP_WAIT0();
        __syncthreads();
        uint32_t stb = sb + (uint32_t)(c & 1) * STAGE_BYTES;
#pragma unroll
        for (int kk = 0; kk < 2; kk++) {
            uint32_t kofA = (uint32_t)kk * 32;
            uint32_t kofB = (uint32_t)kk * bkof;
            uint32_t fa[2][4], fm[2][4];
            ldsm4(fa[0], stb + aoff[0] + kofA);
            ldsm4(fa[1], stb + aoff[1] + kofA);
            ldsm4(fm[0], stb + TEN_BYTES + aoff[0] + kofA);
            ldsm4(fm[1], stb + TEN_BYTES + aoff[1] + kofA);
#pragma unroll
            for (int jp = 0; jp < 4; jp++) {
                uint32_t bh[4], bm2[4];
                if (!btrans) {
                    ldsm4(bh,  stb + 2 * TEN_BYTES + boff[jp] + kofB);
                    ldsm4(bm2, stb + 3 * TEN_BYTES + boff[jp] + kofB);
                } else {
                    ldsm4t(bh,  stb + 2 * TEN_BYTES + boff[jp] + kofB);
                    ldsm4t(bm2, stb + 2 * TEN_BYTES + BT_TEN + boff[jp] + kofB);
                }
                // pass-outer ordering: 4 independent accumulators between RAW reuses
                mma16816(acc[0][2 * jp],     fa[0], &bh[0]);
                mma16816(acc[0][2 * jp + 1], fa[0], &bh[2]);
                mma16816(acc[1][2 * jp],     fa[1], &bh[0]);
                mma16816(acc[1][2 * jp + 1], fa[1], &bh[2]);
                mma16816(acc[0][2 * jp],     fa[0], &bm2[0]);
                mma16816(acc[0][2 * jp + 1], fa[0], &bm2[2]);
                mma16816(acc[1][2 * jp],     fa[1], &bm2[0]);
                mma16816(acc[1][2 * jp + 1], fa[1], &bm2[2]);
                mma16816(acc[0][2 * jp],     fm[0], &bh[0]);
                mma16816(acc[0][2 * jp + 1], fm[0], &bh[2]);
                mma16816(acc[1][2 * jp],     fm[1], &bh[0]);
                mma16816(acc[1][2 * jp + 1], fm[1], &bh[2]);
            }
        }
        __syncthreads();
        if (c + 2 < nch) {
            long ko = (long)(c + 2) * 32;
            uint32_t dstb = sb + (uint32_t)(c & 1) * STAGE_BYTES;
            if (!btrans)
                fill_stage(dstb, Ah + ko, Am + ko, Bh + ko, Bm + ko, sA, sB, tid);
            else
                fill_stage_t(dstb, Ah + ko, Am + ko, Bh + ko * N_, Bm + ko * N_, tid);
            CP_COMMIT();
        }
    }

    // ---------------- epilogue straight from registers ----------------
    int r0 = l >> 2, cp2 = (l & 3) * 2;
    float alpha = (mode == MODE_COMBINE) ? sqrtf(g_s[4 + bz] / g_s[bz]) : 1.0f;

#pragma unroll
    for (int t = 0; t < 2; t++) {
        int gia = i0 + wr * 32 + t * 16 + r0;     // rows gia, gia+8
#pragma unroll
        for (int j = 0; j < 8; j++) {
            int gj = j0 + wc * 64 + j * 8 + cp2;  // cols gj, gj+1
            float v00 = acc[t][j][0], v01 = acc[t][j][1];
            float v10 = acc[t][j][2], v11 = acc[t][j][3];

            if (mode == MODE_COV) {
                // raw partial sums, upper-triangle tiles only (no mirror; cov_reduce resolves)
                float* dst = &g_covp[sK][mz][0];
                *(float2*)&dst[(long)gia * C_ + gj]       = make_float2(v00, v01);
                *(float2*)&dst[(long)(gia + 8) * C_ + gj] = make_float2(v10, v11);
            } else if (mode == MODE_APPLY) {
                float sm0 = g_mean[1][bz][gia], sm1 = g_mean[1][bz][gia + 8];
                float* o0 = outp + ((long)bz * C_ + gia) * N_ + gj;
                *(float2*)o0 = make_float2(v00 + sm0, v01 + sm0);
                float* o1 = outp + ((long)bz * C_ + gia + 8) * N_ + gj;
                *(float2*)o1 = make_float2(v10 + sm1, v11 + sm1);
            } else {
                __nv_bfloat16 *dh, *dm;
                if (mode == MODE_G) {
                    dh = g_Gh[bz]; dm = g_Gm[bz];
                    v00 = -0.5f * v00 + ((gj     == gia)     ? 1.5f : 0.f);
                    v01 = -0.5f * v01 + ((gj + 1 == gia)     ? 1.5f : 0.f);
                    v10 = -0.5f * v10 + ((gj     == gia + 8) ? 1.5f : 0.f);
                    v11 = -0.5f * v11 + ((gj + 1 == gia + 8) ? 1.5f : 0.f);
                } else if (mode == MODE_YZ) {
                    int m = bz & 7;
                    if (bz < 8) { dh = g_Yh[flag ^ 1][m]; dm = g_Ym[flag ^ 1][m]; }
                    else        { dh = g_Zh[flag ^ 1][m]; dm = g_Zm[flag ^ 1][m]; }
                } else if (mode == MODE_YZF) {
                    if (bz < 4) { dh = g_Yh[flag ^ 1][4 + bz]; dm = g_Ym[flag ^ 1][4 + bz]; }
                    else        { dh = g_Zh[flag ^ 1][bz - 4]; dm = g_Zm[flag ^ 1][bz - 4]; }
                } else {
                    dh = g_Mh[bz]; dm = g_Mm[bz];
                    v00 *= alpha; v01 *= alpha; v10 *= alpha; v11 *= alpha;
                }
                __nv_bfloat16 h00, m00, h01, m01, h10, m10, h11, m11;
                split2(v00, h00, m00); split2(v01, h01, m01);
                split2(v10, h10, m10); split2(v11, h11, m11);
                __nv_bfloat162 ph0; ph0.x = h00; ph0.y = h01;
                __nv_bfloat162 pm0; pm0.x = m00; pm0.y = m01;
                __nv_bfloat162 ph1; ph1.x = h10; ph1.y = h11;
                __nv_bfloat162 pm1; pm1.x = m10; pm1.y = m11;
                *(__nv_bfloat162*)&dh[(long)gia * C_ + gj]       = ph0;
                *(__nv_bfloat162*)&dm[(long)gia * C_ + gj]       = pm0;
                *(__nv_bfloat162*)&dh[(long)(gia + 8) * C_ + gj] = ph1;
                *(__nv_bfloat162*)&dm[(long)(gia + 8) * C_ + gj] = pm1;
                if (sym && bx != by) {
                    dh[(long)gj * C_ + gia] = h00;           dm[(long)gj * C_ + gia] = m00;
                    dh[(long)(gj + 1) * C_ + gia] = h01;     dm[(long)(gj + 1) * C_ + gia] = m01;
                    dh[(long)gj * C_ + gia + 8] = h10;       dm[(long)gj * C_ + gia + 8] = m10;
                    dh[(long)(gj + 1) * C_ + gia + 8] = h11; dm[(long)(gj + 1) * C_ + gia + 8] = m11;
                }
            }
        }
    }
}

// ---------------- launch sequence (graph-capturable, deterministic) ----------------
extern "C" void kernel_launch(void* const* d_in, const int* in_sizes, int n_in,
                              void* d_out, int out_size)
{
    const float* content = (const float*)d_in[0];
    const float* style   = (const float*)d_in[1];
    float* out = (float*)d_out;

    cudaFuncSetAttribute(mma_kernel, cudaFuncAttributeMaxDynamicSharedMemorySize, SMEM_DYN);

    means_split_kernel<<<4096, 256>>>(content, style);

    mma_kernel<<<dim3(4, 4, NMAT * KSPLIT), 256, SMEM_DYN>>>(MODE_COV, 0, nullptr);
    cov_reduce_kernel<<<NMAT * C_ * C_ / 256, 256>>>();
    scale_finalize_kernel<<<1, 256>>>();
    init_ns_kernel<<<NMAT * C_ * C_ / 256, 256>>>();   // writes Y0, G1, Z1=G1

    // it0 (flag 0): G1/Z1 already done by init; only Y1 = Y0*G1 (8 Y-jobs)
    mma_kernel<<<dim3(4, 4, NMAT), 256, SMEM_DYN>>>(MODE_YZ, 0, nullptr);
    // it1 (flag 1), it2 (flag 0): full iterations
    for (int it = 1; it < NS_ITERS - 1; it++) {
        mma_kernel<<<dim3(4, 4, NMAT), 256, SMEM_DYN>>>(MODE_G, it & 1, nullptr);
        mma_kernel<<<dim3(4, 4, NMAT * 2), 256, SMEM_DYN>>>(MODE_YZ, it & 1, nullptr);
    }
    // it3 (flag 1): G full, then only Y_style + Z_content (8 jobs); writes buffer [0]
    mma_kernel<<<dim3(4, 4, NMAT), 256, SMEM_DYN>>>(MODE_G, 1, nullptr);
    mma_kernel<<<dim3(4, 4, NMAT), 256, SMEM_DYN>>>(MODE_YZF, 1, nullptr);

    mma_kernel<<<dim3(4, 4, B_), 256, SMEM_DYN>>>(MODE_COMBINE, 0, nullptr);
    mma_kernel<<<dim3(N_ / 128, 4, B_), 256, SMEM_DYN>>>(MODE_APPLY, 0, out);
}